// round 5
// baseline (speedup 1.0000x reference)
#include <cuda_runtime.h>
#include <cuda_bf16.h>
#include <cstddef>

// ---------------- problem constants ----------------
#define NB    8
#define TLEN  2048
#define CDIM  1024
#define FDIM  4096
#define BT    (NB * TLEN)        // 16384 tokens

// ---------------- scratch (static device globals; no allocations allowed) ----
__device__ float g_h [BT * CDIM];
__device__ float g_xk[BT * CDIM];
__device__ float g_xv[BT * CDIM];
__device__ float g_xr[BT * CDIM];
__device__ float g_k [BT * CDIM];
__device__ float g_v [BT * CDIM];
__device__ float g_r [BT * CDIM];
__device__ float g_y [BT * CDIM];
__device__ float g_kk[(size_t)BT * FDIM];
__device__ float g_kv[BT * CDIM];

// ---------------- LayerNorm: one block per token row (C=1024, 256 thr x f4) --
__global__ void __launch_bounds__(256) ln_kernel(const float* __restrict__ x,
                                                 const float* __restrict__ w,
                                                 const float* __restrict__ b,
                                                 float* __restrict__ out) {
    __shared__ float red[16];
    const int row = blockIdx.x;
    const int tid = threadIdx.x;
    const float4* xr = (const float4*)(x + (size_t)row * CDIM);
    float4 v = xr[tid];
    float s = v.x + v.y + v.z + v.w;
    float q = v.x*v.x + v.y*v.y + v.z*v.z + v.w*v.w;
    #pragma unroll
    for (int o = 16; o > 0; o >>= 1) {
        s += __shfl_xor_sync(0xffffffffu, s, o);
        q += __shfl_xor_sync(0xffffffffu, q, o);
    }
    const int lane = tid & 31, wd = tid >> 5;
    if (lane == 0) { red[wd] = s; red[8 + wd] = q; }
    __syncthreads();
    if (tid == 0) {
        float S = 0.f, Q = 0.f;
        #pragma unroll
        for (int i = 0; i < 8; i++) { S += red[i]; Q += red[8 + i]; }
        red[0] = S; red[8] = Q;
    }
    __syncthreads();
    const float mean = red[0] * (1.f / CDIM);
    const float var  = red[8] * (1.f / CDIM) - mean * mean;
    const float rstd = rsqrtf(var + 1e-5f);
    float4 w4 = ((const float4*)w)[tid];
    float4 b4 = ((const float4*)b)[tid];
    float4 o;
    o.x = (v.x - mean) * rstd * w4.x + b4.x;
    o.y = (v.y - mean) * rstd * w4.y + b4.y;
    o.z = (v.z - mean) * rstd * w4.z + b4.z;
    o.w = (v.w - mean) * rstd * w4.w + b4.w;
    ((float4*)(out + (size_t)row * CDIM))[tid] = o;
}

// ---------------- token-shift mixing (3 outputs, attention) ------------------
__global__ void __launch_bounds__(256) mix3_kernel(const float* __restrict__ h,
                                                   const float* __restrict__ tk,
                                                   const float* __restrict__ tv,
                                                   const float* __restrict__ tr,
                                                   float* __restrict__ xk,
                                                   float* __restrict__ xv,
                                                   float* __restrict__ xr) {
    const int idx = blockIdx.x * 256 + threadIdx.x;   // exactly BT*CDIM threads
    const int c = idx & (CDIM - 1);
    const int t = (idx >> 10) & (TLEN - 1);
    const float hv = h[idx];
    const float pv = (t == 0) ? 0.f : h[idx - CDIM];
    const float d = hv - pv;
    xk[idx] = fmaf(tk[c], d, pv);
    xv[idx] = fmaf(tv[c], d, pv);
    xr[idx] = fmaf(tr[c], d, pv);
}

// ---------------- token-shift mixing (2 outputs, FFN) ------------------------
__global__ void __launch_bounds__(256) mix2_kernel(const float* __restrict__ h,
                                                   const float* __restrict__ tk,
                                                   const float* __restrict__ tr,
                                                   float* __restrict__ xk,
                                                   float* __restrict__ xr) {
    const int idx = blockIdx.x * 256 + threadIdx.x;
    const int c = idx & (CDIM - 1);
    const int t = (idx >> 10) & (TLEN - 1);
    const float hv = h[idx];
    const float pv = (t == 0) ? 0.f : h[idx - CDIM];
    const float d = hv - pv;
    xk[idx] = fmaf(tk[c], d, pv);
    xr[idx] = fmaf(tr[c], d, pv);
}

// ---------------- WKV recurrence (one thread per (b,c) lane) -----------------
// y[b,t,c] = sigmoid(r) * wkv;  numerically stable log-sum-exp form, matches ref.
__global__ void __launch_bounds__(64) wkv_kernel(const float* __restrict__ td,
                                                 const float* __restrict__ tf,
                                                 const float* __restrict__ k,
                                                 const float* __restrict__ v,
                                                 const float* __restrict__ r,
                                                 float* __restrict__ y) {
    const int gid = blockIdx.x * 64 + threadIdx.x;    // < NB*CDIM = 8192
    const int c = gid & (CDIM - 1);
    const int b = gid >> 10;
    const float w = -__expf(td[c]);
    const float u = tf[c];
    float aa = 0.f, bb = 0.f, pp = -1e38f;
    size_t base = (size_t)b * TLEN * CDIM + c;
    for (int t = 0; t < TLEN; t++) {
        const size_t i = base + (size_t)t * CDIM;
        const float kt = k[i], vt = v[i];
        const float ww = u + kt;
        const float qq = fmaxf(pp, ww);
        const float e1 = __expf(pp - qq);
        const float e2 = __expf(ww - qq);
        const float yt = (e1 * aa + e2 * vt) / (e1 * bb + e2);
        const float rr = r[i];
        y[i] = yt / (1.f + __expf(-rr));
        const float w2 = pp + w;
        const float q2 = fmaxf(w2, kt);
        const float e1b = __expf(w2 - q2);
        const float e2b = __expf(kt - q2);
        aa = e1b * aa + e2b * vt;
        bb = e1b * bb + e2b;
        pp = q2;
    }
}

// ---------------- SGEMM: C[M,N] = A[M,K] @ B[N,K]^T, fused epilogues ---------
// EPI 0: C = acc
// EPI 1: C = relu(acc)^2
// EPI 2: C = Res + acc
// EPI 3: C = Res + sigmoid(acc) * Aux
template <int EPI>
__global__ void __launch_bounds__(256, 2) sgemm_nt_kernel(
    int M, int N, int K,
    const float* __restrict__ A,
    const float* __restrict__ B,
    float* __restrict__ C,
    const float* __restrict__ Res,
    const float* __restrict__ Aux) {
    __shared__ float As[8][128];
    __shared__ float Bs[8][128];

    const int tid  = threadIdx.x;
    const int tx   = tid & 15;       // N direction (x8)
    const int ty   = tid >> 4;       // M direction (x8)
    const int arow = tid >> 1;       // 0..127 tile row for loads
    const int acol = (tid & 1) << 2; // 0 or 4 (k offset)

    const float* Ag = A + (size_t)(blockIdx.y * 128 + arow) * K + acol;
    const float* Bg = B + (size_t)(blockIdx.x * 128 + arow) * K + acol;

    float acc[8][8];
    #pragma unroll
    for (int i = 0; i < 8; i++)
        #pragma unroll
        for (int j = 0; j < 8; j++) acc[i][j] = 0.f;

    float4 a4 = *(const float4*)Ag;
    float4 b4 = *(const float4*)Bg;

    for (int k0 = 0; k0 < K; k0 += 8) {
        As[acol + 0][arow] = a4.x; As[acol + 1][arow] = a4.y;
        As[acol + 2][arow] = a4.z; As[acol + 3][arow] = a4.w;
        Bs[acol + 0][arow] = b4.x; Bs[acol + 1][arow] = b4.y;
        Bs[acol + 2][arow] = b4.z; Bs[acol + 3][arow] = b4.w;
        __syncthreads();
        if (k0 + 8 < K) {                     // prefetch next tile into regs
            a4 = *(const float4*)(Ag + k0 + 8);
            b4 = *(const float4*)(Bg + k0 + 8);
        }
        #pragma unroll
        for (int kk = 0; kk < 8; kk++) {
            float ra[8], rb[8];
            #pragma unroll
            for (int i = 0; i < 8; i++) ra[i] = As[kk][ty * 8 + i];
            #pragma unroll
            for (int j = 0; j < 8; j++) rb[j] = Bs[kk][tx * 8 + j];
            #pragma unroll
            for (int i = 0; i < 8; i++)
                #pragma unroll
                for (int j = 0; j < 8; j++)
                    acc[i][j] = fmaf(ra[i], rb[j], acc[i][j]);
        }
        __syncthreads();
    }

    const int m0 = blockIdx.y * 128 + ty * 8;
    const int n0 = blockIdx.x * 128 + tx * 8;
    #pragma unroll
    for (int i = 0; i < 8; i++) {
        const size_t roff = (size_t)(m0 + i) * N + n0;
        #pragma unroll
        for (int jv = 0; jv < 2; jv++) {
            const float* pa = &acc[i][jv * 4];
            float4 o;
            if (EPI == 0) {
                o = make_float4(pa[0], pa[1], pa[2], pa[3]);
            } else if (EPI == 1) {
                float r0 = fmaxf(pa[0], 0.f), r1 = fmaxf(pa[1], 0.f);
                float r2 = fmaxf(pa[2], 0.f), r3 = fmaxf(pa[3], 0.f);
                o = make_float4(r0 * r0, r1 * r1, r2 * r2, r3 * r3);
            } else if (EPI == 2) {
                float4 rs = *(const float4*)(Res + roff + jv * 4);
                o = make_float4(rs.x + pa[0], rs.y + pa[1],
                                rs.z + pa[2], rs.w + pa[3]);
            } else {
                float4 rs = *(const float4*)(Res + roff + jv * 4);
                float4 ax = *(const float4*)(Aux + roff + jv * 4);
                o.x = rs.x + ax.x / (1.f + __expf(-pa[0]));
                o.y = rs.y + ax.y / (1.f + __expf(-pa[1]));
                o.z = rs.z + ax.z / (1.f + __expf(-pa[2]));
                o.w = rs.w + ax.w / (1.f + __expf(-pa[3]));
            }
            *(float4*)(C + roff + jv * 4) = o;
        }
    }
}

// ---------------- host orchestration ----------------------------------------
extern "C" void kernel_launch(void* const* d_in, const int* in_sizes, int n_in,
                              void* d_out, int out_size) {
    const float* x     = (const float*)d_in[0];
    const float* ln1w  = (const float*)d_in[1];
    const float* ln1b  = (const float*)d_in[2];
    const float* ln2w  = (const float*)d_in[3];
    const float* ln2b  = (const float*)d_in[4];
    const float* atmk  = (const float*)d_in[5];
    const float* atmv  = (const float*)d_in[6];
    const float* atmr  = (const float*)d_in[7];
    const float* tdec  = (const float*)d_in[8];
    const float* tfst  = (const float*)d_in[9];
    const float* Wk    = (const float*)d_in[10];
    const float* Wv    = (const float*)d_in[11];
    const float* Wr    = (const float*)d_in[12];
    const float* Wo    = (const float*)d_in[13];
    const float* ftmk  = (const float*)d_in[14];
    const float* ftmr  = (const float*)d_in[15];
    const float* Wkey  = (const float*)d_in[16];
    const float* Wrec  = (const float*)d_in[17];
    const float* Wval  = (const float*)d_in[18];
    float* out = (float*)d_out;

    float *h, *xk, *xv, *xr, *kb, *vb, *rb, *yb, *kkb, *kvb;
    cudaGetSymbolAddress((void**)&h,   g_h);
    cudaGetSymbolAddress((void**)&xk,  g_xk);
    cudaGetSymbolAddress((void**)&xv,  g_xv);
    cudaGetSymbolAddress((void**)&xr,  g_xr);
    cudaGetSymbolAddress((void**)&kb,  g_k);
    cudaGetSymbolAddress((void**)&vb,  g_v);
    cudaGetSymbolAddress((void**)&rb,  g_r);
    cudaGetSymbolAddress((void**)&yb,  g_y);
    cudaGetSymbolAddress((void**)&kkb, g_kk);
    cudaGetSymbolAddress((void**)&kvb, g_kv);

    const int elemBlocks = (BT * CDIM) / 256;        // 65536
    const dim3 gC(CDIM / 128, BT / 128);             // (8, 128)
    const dim3 gF(FDIM / 128, BT / 128);             // (32, 128)

    // ---- attention half ----
    ln_kernel<<<BT, 256>>>(x, ln1w, ln1b, h);
    mix3_kernel<<<elemBlocks, 256>>>(h, atmk, atmv, atmr, xk, xv, xr);
    sgemm_nt_kernel<0><<<gC, 256>>>(BT, CDIM, CDIM, xk, Wk, kb, nullptr, nullptr);
    sgemm_nt_kernel<0><<<gC, 256>>>(BT, CDIM, CDIM, xv, Wv, vb, nullptr, nullptr);
    sgemm_nt_kernel<0><<<gC, 256>>>(BT, CDIM, CDIM, xr, Wr, rb, nullptr, nullptr);
    wkv_kernel<<<(NB * CDIM) / 64, 64>>>(tdec, tfst, kb, vb, rb, yb);
    sgemm_nt_kernel<2><<<gC, 256>>>(BT, CDIM, CDIM, yb, Wo, out, x, nullptr);

    // ---- FFN half ----
    ln_kernel<<<BT, 256>>>(out, ln2w, ln2b, h);
    mix2_kernel<<<elemBlocks, 256>>>(h, ftmk, ftmr, xk, xr);
    sgemm_nt_kernel<1><<<gF, 256>>>(BT, FDIM, CDIM, xk, Wkey, kkb, nullptr, nullptr);
    sgemm_nt_kernel<0><<<gC, 256>>>(BT, CDIM, FDIM, kkb, Wval, kvb, nullptr, nullptr);
    sgemm_nt_kernel<3><<<gC, 256>>>(BT, CDIM, CDIM, xr, Wrec, out, out, kvb);
}

// round 9
// speedup vs baseline: 1.7373x; 1.7373x over previous
#include <cuda_runtime.h>
#include <cuda_bf16.h>
#include <cstdint>
#include <cstddef>

// ---------------- problem constants ----------------
#define NB    8
#define TLEN  2048
#define CDIM  1024
#define FDIM  4096
#define BT    (NB * TLEN)        // 16384 tokens

// ---------------- scratch (static device globals; no allocations allowed) ----
__device__ float g_h [BT * CDIM];
__device__ float g_xk[BT * CDIM];
__device__ float g_xv[BT * CDIM];
__device__ float g_xr[BT * CDIM];
__device__ float g_k [BT * CDIM];
__device__ float g_v [BT * CDIM];
__device__ float g_r [BT * CDIM];
__device__ float g_y [BT * CDIM];
__device__ float g_kk[(size_t)BT * FDIM];
__device__ float g_kv[BT * CDIM];

// ============================================================================
// helpers
// ============================================================================
__device__ __forceinline__ uint32_t smem_u32(const void* p) {
    uint32_t a;
    asm("{ .reg .u64 t; cvta.to.shared.u64 t, %1; cvt.u32.u64 %0, t; }"
        : "=r"(a) : "l"(p));
    return a;
}

__device__ __forceinline__ void ldsm_x4(uint32_t* r, uint32_t addr) {
    asm volatile("ldmatrix.sync.aligned.m8n8.x4.shared.b16 {%0,%1,%2,%3}, [%4];"
        : "=r"(r[0]), "=r"(r[1]), "=r"(r[2]), "=r"(r[3]) : "r"(addr));
}

__device__ __forceinline__ void mma16816(float* d, const uint32_t* a,
                                         const uint32_t* b) {
    asm volatile("mma.sync.aligned.m16n8k16.row.col.f32.bf16.bf16.f32 "
        "{%0,%1,%2,%3}, {%4,%5,%6,%7}, {%8,%9}, {%0,%1,%2,%3};"
        : "+f"(d[0]), "+f"(d[1]), "+f"(d[2]), "+f"(d[3])
        : "r"(a[0]), "r"(a[1]), "r"(a[2]), "r"(a[3]), "r"(b[0]), "r"(b[1]));
}

// convert float4 -> bf16 hi (truncate) + bf16 lo (exact residual, rn), store
__device__ __forceinline__ void cvst(uint32_t hA, uint32_t lA, float4 a) {
    uint32_t u0 = __float_as_uint(a.x), u1 = __float_as_uint(a.y);
    uint32_t u2 = __float_as_uint(a.z), u3 = __float_as_uint(a.w);
    uint32_t hi01 = __byte_perm(u0, u1, 0x7632);
    uint32_t hi23 = __byte_perm(u2, u3, 0x7632);
    float l0 = a.x - __uint_as_float(u0 & 0xFFFF0000u);
    float l1 = a.y - __uint_as_float(u1 & 0xFFFF0000u);
    float l2 = a.z - __uint_as_float(u2 & 0xFFFF0000u);
    float l3 = a.w - __uint_as_float(u3 & 0xFFFF0000u);
    uint32_t lo01, lo23;
    asm("cvt.rn.satfinite.bf16x2.f32 %0, %1, %2;" : "=r"(lo01) : "f"(l1), "f"(l0));
    asm("cvt.rn.satfinite.bf16x2.f32 %0, %1, %2;" : "=r"(lo23) : "f"(l3), "f"(l2));
    asm volatile("st.shared.v2.b32 [%0], {%1, %2};"
                 :: "r"(hA), "r"(hi01), "r"(hi23) : "memory");
    asm volatile("st.shared.v2.b32 [%0], {%1, %2};"
                 :: "r"(lA), "r"(lo01), "r"(lo23) : "memory");
}

// ============================================================================
// HMMA GEMM: C[M,N] = A[M,K] @ B[N,K]^T   (bf16 hi/lo 3-pass, fp32 accum)
// BM=128, BN=128, BK=32; 8 warps 4(m) x 2(n); double-buffered SMEM.
// EPI 0: C=acc  1: C=relu(acc)^2  2: C=Res+acc  3: C=Res+sigmoid(acc)*Aux
// ============================================================================
#define ROWB   80                    // bytes per SMEM row (32 bf16 + 4 pad)
#define A_HI   0
#define A_LO   10240
#define B_HI   20480
#define B_LO   30720
#define STG_BYTES 40960
#define GEMM_SMEM_BYTES (2 * STG_BYTES)

template <int EPI>
__global__ void __launch_bounds__(256, 1) hmma_gemm_kernel(
    int M, int N, int K,
    const float* __restrict__ A,
    const float* __restrict__ B,
    float* __restrict__ C,
    const float* __restrict__ Res,
    const float* __restrict__ Aux)
{
    extern __shared__ __align__(128) char dynsmem[];
    const uint32_t sm = smem_u32(dynsmem);
    const int tid = threadIdx.x;
    const int wid = tid >> 5, lid = tid & 31;
    const int wm = wid >> 1, wn = wid & 1;

    const float* Abase = A + (size_t)(blockIdx.y * 128) * K;
    const float* Bbase = B + (size_t)(blockIdx.x * 128) * K;

    // global-load mapping: 4 float4 each for A and B per stage
    const int lrow = tid >> 3;       // 0..31, +32*i
    const int lkq  = tid & 7;        // float4 within 32-elem k row

    float acc[2][8][4];
    #pragma unroll
    for (int f = 0; f < 2; f++)
        #pragma unroll
        for (int j = 0; j < 8; j++)
            #pragma unroll
            for (int c = 0; c < 4; c++) acc[f][j][c] = 0.f;

    float4 pa[4], pb[4];
    const int ns = K >> 5;           // K / 32

    // prologue: stage 0
    #pragma unroll
    for (int i = 0; i < 4; i++) {
        pa[i] = *(const float4*)(Abase + (size_t)(lrow + 32 * i) * K + lkq * 4);
        pb[i] = *(const float4*)(Bbase + (size_t)(lrow + 32 * i) * K + lkq * 4);
    }
    {
        const uint32_t base = sm;
        #pragma unroll
        for (int i = 0; i < 4; i++) {
            const uint32_t off = (lrow + 32 * i) * ROWB + lkq * 8;
            cvst(base + A_HI + off, base + A_LO + off, pa[i]);
            cvst(base + B_HI + off, base + B_LO + off, pb[i]);
        }
    }
    __syncthreads();

    // per-lane ldmatrix offsets
    const uint32_t lrow16 = (lid & 15);
    const uint32_t lhi16  = (lid >> 4) * 16;   // +16B for k8-15 matrices

    for (int s = 0; s < ns; s++) {
        if (s + 1 < ns) {            // issue next-stage global loads early
            const float* Ag = Abase + (s + 1) * 32;
            const float* Bg = Bbase + (s + 1) * 32;
            #pragma unroll
            for (int i = 0; i < 4; i++) {
                pa[i] = *(const float4*)(Ag + (size_t)(lrow + 32 * i) * K + lkq * 4);
                pb[i] = *(const float4*)(Bg + (size_t)(lrow + 32 * i) * K + lkq * 4);
            }
        }

        const uint32_t base = sm + (s & 1) * STG_BYTES;
        #pragma unroll
        for (int ks = 0; ks < 2; ks++) {
            const uint32_t kb = ks * 32 + lhi16;
            uint32_t ah[2][4], al[2][4], bh[4][4], bl[4][4];
            const uint32_t arow = wm * 32 + lrow16;
            ldsm_x4(ah[0], base + A_HI + arow * ROWB + kb);
            ldsm_x4(ah[1], base + A_HI + (arow + 16) * ROWB + kb);
            ldsm_x4(al[0], base + A_LO + arow * ROWB + kb);
            ldsm_x4(al[1], base + A_LO + (arow + 16) * ROWB + kb);
            const uint32_t brow = wn * 64 + lrow16;
            #pragma unroll
            for (int nb = 0; nb < 4; nb++) {
                ldsm_x4(bh[nb], base + B_HI + (brow + nb * 16) * ROWB + kb);
                ldsm_x4(bl[nb], base + B_LO + (brow + nb * 16) * ROWB + kb);
            }
            #pragma unroll
            for (int f = 0; f < 2; f++) {
                #pragma unroll
                for (int j = 0; j < 8; j++) {
                    const int nb = j >> 1, sl = j & 1;
                    uint32_t bfh[2] = { bh[nb][sl], bh[nb][sl + 2] };
                    uint32_t bfl[2] = { bl[nb][sl], bl[nb][sl + 2] };
                    mma16816(acc[f][j], ah[f], bfh);   // hi*hi
                    mma16816(acc[f][j], ah[f], bfl);   // hi*lo
                    mma16816(acc[f][j], al[f], bfh);   // lo*hi
                }
            }
        }

        if (s + 1 < ns) {
            __syncthreads();         // all warps done reading buf (s+1)&1
            const uint32_t nb2 = sm + ((s + 1) & 1) * STG_BYTES;
            #pragma unroll
            for (int i = 0; i < 4; i++) {
                const uint32_t off = (lrow + 32 * i) * ROWB + lkq * 8;
                cvst(nb2 + A_HI + off, nb2 + A_LO + off, pa[i]);
                cvst(nb2 + B_HI + off, nb2 + B_LO + off, pb[i]);
            }
            __syncthreads();         // stores visible before next compute
        }
    }

    // ---- epilogue: direct register -> global, fused ----
    const int r0 = lid >> 2;
    const int c0 = (lid & 3) * 2;
    #pragma unroll
    for (int f = 0; f < 2; f++) {
        #pragma unroll
        for (int j = 0; j < 8; j++) {
            const int row = blockIdx.y * 128 + wm * 32 + f * 16 + r0;
            const int col = blockIdx.x * 128 + wn * 64 + j * 8 + c0;
            #pragma unroll
            for (int hh = 0; hh < 2; hh++) {
                const size_t goff = (size_t)(row + hh * 8) * N + col;
                float p0 = acc[f][j][hh * 2 + 0];
                float p1 = acc[f][j][hh * 2 + 1];
                float2 o;
                if (EPI == 0) {
                    o = make_float2(p0, p1);
                } else if (EPI == 1) {
                    float a0 = fmaxf(p0, 0.f), a1 = fmaxf(p1, 0.f);
                    o = make_float2(a0 * a0, a1 * a1);
                } else if (EPI == 2) {
                    float2 rs = *(const float2*)(Res + goff);
                    o = make_float2(rs.x + p0, rs.y + p1);
                } else {
                    float2 rs = *(const float2*)(Res + goff);
                    float2 ax = *(const float2*)(Aux + goff);
                    o.x = rs.x + ax.x / (1.f + __expf(-p0));
                    o.y = rs.y + ax.y / (1.f + __expf(-p1));
                }
                *(float2*)(C + goff) = o;
            }
        }
    }
}

// ---------------- LayerNorm: one block per token row (C=1024, 256 thr x f4) --
__global__ void __launch_bounds__(256) ln_kernel(const float* __restrict__ x,
                                                 const float* __restrict__ w,
                                                 const float* __restrict__ b,
                                                 float* __restrict__ out) {
    __shared__ float red[16];
    const int row = blockIdx.x;
    const int tid = threadIdx.x;
    const float4* xr = (const float4*)(x + (size_t)row * CDIM);
    float4 v = xr[tid];
    float s = v.x + v.y + v.z + v.w;
    float q = v.x*v.x + v.y*v.y + v.z*v.z + v.w*v.w;
    #pragma unroll
    for (int o = 16; o > 0; o >>= 1) {
        s += __shfl_xor_sync(0xffffffffu, s, o);
        q += __shfl_xor_sync(0xffffffffu, q, o);
    }
    const int lane = tid & 31, wd = tid >> 5;
    if (lane == 0) { red[wd] = s; red[8 + wd] = q; }
    __syncthreads();
    if (tid == 0) {
        float S = 0.f, Q = 0.f;
        #pragma unroll
        for (int i = 0; i < 8; i++) { S += red[i]; Q += red[8 + i]; }
        red[0] = S; red[8] = Q;
    }
    __syncthreads();
    const float mean = red[0] * (1.f / CDIM);
    const float var  = red[8] * (1.f / CDIM) - mean * mean;
    const float rstd = rsqrtf(var + 1e-5f);
    float4 w4 = ((const float4*)w)[tid];
    float4 b4 = ((const float4*)b)[tid];
    float4 o;
    o.x = (v.x - mean) * rstd * w4.x + b4.x;
    o.y = (v.y - mean) * rstd * w4.y + b4.y;
    o.z = (v.z - mean) * rstd * w4.z + b4.z;
    o.w = (v.w - mean) * rstd * w4.w + b4.w;
    ((float4*)(out + (size_t)row * CDIM))[tid] = o;
}

// ---------------- token-shift mixing (3 outputs, attention) ------------------
__global__ void __launch_bounds__(256) mix3_kernel(const float* __restrict__ h,
                                                   const float* __restrict__ tk,
                                                   const float* __restrict__ tv,
                                                   const float* __restrict__ tr,
                                                   float* __restrict__ xk,
                                                   float* __restrict__ xv,
                                                   float* __restrict__ xr) {
    const int idx = blockIdx.x * 256 + threadIdx.x;
    const int c = idx & (CDIM - 1);
    const int t = (idx >> 10) & (TLEN - 1);
    const float hv = h[idx];
    const float pv = (t == 0) ? 0.f : h[idx - CDIM];
    const float d = hv - pv;
    xk[idx] = fmaf(tk[c], d, pv);
    xv[idx] = fmaf(tv[c], d, pv);
    xr[idx] = fmaf(tr[c], d, pv);
}

// ---------------- token-shift mixing (2 outputs, FFN) ------------------------
__global__ void __launch_bounds__(256) mix2_kernel(const float* __restrict__ h,
                                                   const float* __restrict__ tk,
                                                   const float* __restrict__ tr,
                                                   float* __restrict__ xk,
                                                   float* __restrict__ xr) {
    const int idx = blockIdx.x * 256 + threadIdx.x;
    const int c = idx & (CDIM - 1);
    const int t = (idx >> 10) & (TLEN - 1);
    const float hv = h[idx];
    const float pv = (t == 0) ? 0.f : h[idx - CDIM];
    const float d = hv - pv;
    xk[idx] = fmaf(tk[c], d, pv);
    xr[idx] = fmaf(tr[c], d, pv);
}

// ---------------- WKV recurrence (one thread per (b,c) lane) -----------------
__global__ void __launch_bounds__(64) wkv_kernel(const float* __restrict__ td,
                                                 const float* __restrict__ tf,
                                                 const float* __restrict__ k,
                                                 const float* __restrict__ v,
                                                 const float* __restrict__ r,
                                                 float* __restrict__ y) {
    const int gid = blockIdx.x * 64 + threadIdx.x;
    const int c = gid & (CDIM - 1);
    const int b = gid >> 10;
    const float w = -__expf(td[c]);
    const float u = tf[c];
    float aa = 0.f, bb = 0.f, pp = -1e38f;
    size_t base = (size_t)b * TLEN * CDIM + c;
    for (int t = 0; t < TLEN; t++) {
        const size_t i = base + (size_t)t * CDIM;
        const float kt = k[i], vt = v[i];
        const float ww = u + kt;
        const float qq = fmaxf(pp, ww);
        const float e1 = __expf(pp - qq);
        const float e2 = __expf(ww - qq);
        const float yt = (e1 * aa + e2 * vt) / (e1 * bb + e2);
        const float rr = r[i];
        y[i] = yt / (1.f + __expf(-rr));
        const float w2 = pp + w;
        const float q2 = fmaxf(w2, kt);
        const float e1b = __expf(w2 - q2);
        const float e2b = __expf(kt - q2);
        aa = e1b * aa + e2b * vt;
        bb = e1b * bb + e2b;
        pp = q2;
    }
}

// ---------------- host orchestration ----------------------------------------
extern "C" void kernel_launch(void* const* d_in, const int* in_sizes, int n_in,
                              void* d_out, int out_size) {
    const float* x     = (const float*)d_in[0];
    const float* ln1w  = (const float*)d_in[1];
    const float* ln1b  = (const float*)d_in[2];
    const float* ln2w  = (const float*)d_in[3];
    const float* ln2b  = (const float*)d_in[4];
    const float* atmk  = (const float*)d_in[5];
    const float* atmv  = (const float*)d_in[6];
    const float* atmr  = (const float*)d_in[7];
    const float* tdec  = (const float*)d_in[8];
    const float* tfst  = (const float*)d_in[9];
    const float* Wk    = (const float*)d_in[10];
    const float* Wv    = (const float*)d_in[11];
    const float* Wr    = (const float*)d_in[12];
    const float* Wo    = (const float*)d_in[13];
    const float* ftmk  = (const float*)d_in[14];
    const float* ftmr  = (const float*)d_in[15];
    const float* Wkey  = (const float*)d_in[16];
    const float* Wrec  = (const float*)d_in[17];
    const float* Wval  = (const float*)d_in[18];
    float* out = (float*)d_out;

    float *h, *xk, *xv, *xr, *kb, *vb, *rb, *yb, *kkb, *kvb;
    cudaGetSymbolAddress((void**)&h,   g_h);
    cudaGetSymbolAddress((void**)&xk,  g_xk);
    cudaGetSymbolAddress((void**)&xv,  g_xv);
    cudaGetSymbolAddress((void**)&xr,  g_xr);
    cudaGetSymbolAddress((void**)&kb,  g_k);
    cudaGetSymbolAddress((void**)&vb,  g_v);
    cudaGetSymbolAddress((void**)&rb,  g_r);
    cudaGetSymbolAddress((void**)&yb,  g_y);
    cudaGetSymbolAddress((void**)&kkb, g_kk);
    cudaGetSymbolAddress((void**)&kvb, g_kv);

    cudaFuncSetAttribute(hmma_gemm_kernel<0>, cudaFuncAttributeMaxDynamicSharedMemorySize, GEMM_SMEM_BYTES);
    cudaFuncSetAttribute(hmma_gemm_kernel<1>, cudaFuncAttributeMaxDynamicSharedMemorySize, GEMM_SMEM_BYTES);
    cudaFuncSetAttribute(hmma_gemm_kernel<2>, cudaFuncAttributeMaxDynamicSharedMemorySize, GEMM_SMEM_BYTES);
    cudaFuncSetAttribute(hmma_gemm_kernel<3>, cudaFuncAttributeMaxDynamicSharedMemorySize, GEMM_SMEM_BYTES);

    const int elemBlocks = (BT * CDIM) / 256;        // 65536
    const dim3 gC(CDIM / 128, BT / 128);             // (8, 128)
    const dim3 gF(FDIM / 128, BT / 128);             // (32, 128)

    // ---- attention half ----
    ln_kernel<<<BT, 256>>>(x, ln1w, ln1b, h);
    mix3_kernel<<<elemBlocks, 256>>>(h, atmk, atmv, atmr, xk, xv, xr);
    hmma_gemm_kernel<0><<<gC, 256, GEMM_SMEM_BYTES>>>(BT, CDIM, CDIM, xk, Wk, kb, nullptr, nullptr);
    hmma_gemm_kernel<0><<<gC, 256, GEMM_SMEM_BYTES>>>(BT, CDIM, CDIM, xv, Wv, vb, nullptr, nullptr);
    hmma_gemm_kernel<0><<<gC, 256, GEMM_SMEM_BYTES>>>(BT, CDIM, CDIM, xr, Wr, rb, nullptr, nullptr);
    wkv_kernel<<<(NB * CDIM) / 64, 64>>>(tdec, tfst, kb, vb, rb, yb);
    hmma_gemm_kernel<2><<<gC, 256, GEMM_SMEM_BYTES>>>(BT, CDIM, CDIM, yb, Wo, out, x, nullptr);

    // ---- FFN half ----
    ln_kernel<<<BT, 256>>>(out, ln2w, ln2b, h);
    mix2_kernel<<<elemBlocks, 256>>>(h, ftmk, ftmr, xk, xr);
    hmma_gemm_kernel<1><<<gF, 256, GEMM_SMEM_BYTES>>>(BT, FDIM, CDIM, xk, Wkey, kkb, nullptr, nullptr);
    hmma_gemm_kernel<0><<<gC, 256, GEMM_SMEM_BYTES>>>(BT, CDIM, FDIM, kkb, Wval, kvb, nullptr, nullptr);
    hmma_gemm_kernel<3><<<gC, 256, GEMM_SMEM_BYTES>>>(BT, CDIM, CDIM, xr, Wrec, out, out, kvb);
}

// round 10
// speedup vs baseline: 2.3151x; 1.3326x over previous
#include <cuda_runtime.h>
#include <cuda_bf16.h>
#include <cstdint>
#include <cstddef>

// ---------------- problem constants ----------------
#define NB    8
#define TLEN  2048
#define CDIM  1024
#define FDIM  4096
#define BT    (NB * TLEN)        // 16384 tokens

typedef unsigned short ushort16;

// ---------------- scratch (static device globals; no allocations allowed) ----
__device__ float g_h [BT * CDIM];
__device__ float g_k [BT * CDIM];
__device__ float g_v [BT * CDIM];
__device__ float g_r [BT * CDIM];
__device__ float g_kv[BT * CDIM];
__device__ ushort16 g_xk_h[BT * CDIM], g_xk_l[BT * CDIM];
__device__ ushort16 g_xv_h[BT * CDIM], g_xv_l[BT * CDIM];
__device__ ushort16 g_xr_h[BT * CDIM], g_xr_l[BT * CDIM];
__device__ ushort16 g_y_h [BT * CDIM], g_y_l [BT * CDIM];
__device__ ushort16 g_kk_h[(size_t)BT * FDIM], g_kk_l[(size_t)BT * FDIM];
__device__ ushort16 g_w_h[13631488], g_w_l[13631488];   // 13M weight elems

// ============================================================================
// helpers
// ============================================================================
__device__ __forceinline__ uint32_t smem_u32(const void* p) {
    uint32_t a;
    asm("{ .reg .u64 t; cvta.to.shared.u64 t, %1; cvt.u32.u64 %0, t; }"
        : "=r"(a) : "l"(p));
    return a;
}
__device__ __forceinline__ void ldsm_x4(uint32_t* r, uint32_t addr) {
    asm volatile("ldmatrix.sync.aligned.m8n8.x4.shared.b16 {%0,%1,%2,%3}, [%4];"
        : "=r"(r[0]), "=r"(r[1]), "=r"(r[2]), "=r"(r[3]) : "r"(addr));
}
__device__ __forceinline__ void mma16816(float* d, const uint32_t* a,
                                         const uint32_t* b) {
    asm volatile("mma.sync.aligned.m16n8k16.row.col.f32.bf16.bf16.f32 "
        "{%0,%1,%2,%3}, {%4,%5,%6,%7}, {%8,%9}, {%0,%1,%2,%3};"
        : "+f"(d[0]), "+f"(d[1]), "+f"(d[2]), "+f"(d[3])
        : "r"(a[0]), "r"(a[1]), "r"(a[2]), "r"(a[3]), "r"(b[0]), "r"(b[1]));
}
__device__ __forceinline__ void split_store(ushort16* __restrict__ hp,
                                            ushort16* __restrict__ lp,
                                            size_t i, float x) {
    const uint32_t u = __float_as_uint(x);
    hp[i] = (ushort16)(u >> 16);
    const float lo = x - __uint_as_float(u & 0xFFFF0000u);
    __nv_bfloat16 b = __float2bfloat16(lo);
    lp[i] = *reinterpret_cast<ushort16*>(&b);
}

// ============================================================================
// HMMA GEMM: C[M,N] = A[M,K] @ B[N,K]^T  from pre-split bf16 hi/lo planes.
// BM=128, BN=128, BK=32; 8 warps 4(m) x 2(n); 4-stage cp.async pipeline.
// EPI 0: C=acc  1: {Ohi,Olo}=split(relu(acc)^2)  2: C=Res+acc
// EPI 3: C=Res+sigmoid(acc)*Aux
// ============================================================================
#define ROWB        80               // 32 bf16 (64B) + 16B pad per SMEM row
#define PLANE_BYTES 10240            // 128 * 80
#define STG_BYTES   40960            // 4 planes (A_hi, A_lo, B_hi, B_lo)
#define NSTAGE      4
#define GEMM_SMEM_BYTES (NSTAGE * STG_BYTES)   // 163840

template <int EPI>
__global__ void __launch_bounds__(256, 1) hmma_gemm_kernel(
    int M, int N, int K,
    const ushort16* __restrict__ Ah, const ushort16* __restrict__ Al,
    const ushort16* __restrict__ Bh, const ushort16* __restrict__ Bl,
    float* __restrict__ C,
    ushort16* __restrict__ Ohi, ushort16* __restrict__ Olo,
    const float* __restrict__ Res,
    const float* __restrict__ Aux)
{
    extern __shared__ __align__(128) char dynsmem[];
    const uint32_t sm = smem_u32(dynsmem);
    const int tid = threadIdx.x;
    const int wid = tid >> 5, lid = tid & 31;
    const int wm = wid >> 1, wn = wid & 1;

    const ushort16* gp0 = Ah + (size_t)(blockIdx.y * 128) * K;
    const ushort16* gp1 = Al + (size_t)(blockIdx.y * 128) * K;
    const ushort16* gp2 = Bh + (size_t)(blockIdx.x * 128) * K;
    const ushort16* gp3 = Bl + (size_t)(blockIdx.x * 128) * K;

    float acc[2][8][4];
    #pragma unroll
    for (int f = 0; f < 2; f++)
        #pragma unroll
        for (int j = 0; j < 8; j++)
            #pragma unroll
            for (int c = 0; c < 4; c++) acc[f][j][c] = 0.f;

    const int ns = K >> 5;           // K / 32

    // cp.async fill of one stage: 4 planes x 128 rows x 64B = 2048 x 16B chunks
    auto issue = [&](int s) {
        const uint32_t base = sm + (s & 3) * STG_BYTES;
        #pragma unroll
        for (int i = 0; i < 8; i++) {
            const int plane = i >> 1;
            const int idx2 = ((i & 1) << 8) | tid;     // 0..511 within plane
            const int row = idx2 >> 2;
            const int kq  = idx2 & 3;                  // 16B chunk in k-row
            const ushort16* src =
                (plane == 0 ? gp0 : plane == 1 ? gp1 : plane == 2 ? gp2 : gp3)
                + (size_t)row * K + s * 32 + kq * 8;
            const uint32_t dst = base + plane * PLANE_BYTES + row * ROWB + kq * 16;
            asm volatile("cp.async.cg.shared.global [%0], [%1], 16;"
                         :: "r"(dst), "l"(src) : "memory");
        }
        asm volatile("cp.async.commit_group;" ::: "memory");
    };

    issue(0); issue(1); issue(2);

    const uint32_t lrow16 = (lid & 15);
    const uint32_t lhi16  = (lid >> 4) * 16;           // +16B for k8..15 mats

    for (int s = 0; s < ns; s++) {
        asm volatile("cp.async.wait_group 2;" ::: "memory");
        __syncthreads();
        if (s + 3 < ns) issue(s + 3);

        const uint32_t base = sm + (s & 3) * STG_BYTES;
        #pragma unroll
        for (int ks = 0; ks < 2; ks++) {
            const uint32_t kb = ks * 32 + lhi16;
            uint32_t ah[2][4], al[2][4], bh[4][4], bl[4][4];
            const uint32_t arow = wm * 32 + lrow16;
            ldsm_x4(ah[0], base + 0 * PLANE_BYTES + arow * ROWB + kb);
            ldsm_x4(ah[1], base + 0 * PLANE_BYTES + (arow + 16) * ROWB + kb);
            ldsm_x4(al[0], base + 1 * PLANE_BYTES + arow * ROWB + kb);
            ldsm_x4(al[1], base + 1 * PLANE_BYTES + (arow + 16) * ROWB + kb);
            const uint32_t brow = wn * 64 + lrow16;
            #pragma unroll
            for (int nb = 0; nb < 4; nb++) {
                ldsm_x4(bh[nb], base + 2 * PLANE_BYTES + (brow + nb * 16) * ROWB + kb);
                ldsm_x4(bl[nb], base + 3 * PLANE_BYTES + (brow + nb * 16) * ROWB + kb);
            }
            #pragma unroll
            for (int f = 0; f < 2; f++) {
                #pragma unroll
                for (int j = 0; j < 8; j++) {
                    const int nb = j >> 1, sl = j & 1;
                    uint32_t bfh[2] = { bh[nb][sl], bh[nb][sl + 2] };
                    uint32_t bfl[2] = { bl[nb][sl], bl[nb][sl + 2] };
                    mma16816(acc[f][j], ah[f], bfh);   // hi*hi
                    mma16816(acc[f][j], ah[f], bfl);   // hi*lo
                    mma16816(acc[f][j], al[f], bfh);   // lo*hi
                }
            }
        }
    }

    // ---- epilogue: direct register -> global, fused ----
    const int r0 = lid >> 2;
    const int c0 = (lid & 3) * 2;
    #pragma unroll
    for (int f = 0; f < 2; f++) {
        #pragma unroll
        for (int j = 0; j < 8; j++) {
            const int row = blockIdx.y * 128 + wm * 32 + f * 16 + r0;
            const int col = blockIdx.x * 128 + wn * 64 + j * 8 + c0;
            #pragma unroll
            for (int hh = 0; hh < 2; hh++) {
                const size_t goff = (size_t)(row + hh * 8) * N + col;
                float p0 = acc[f][j][hh * 2 + 0];
                float p1 = acc[f][j][hh * 2 + 1];
                if (EPI == 1) {
                    float a0 = fmaxf(p0, 0.f), a1 = fmaxf(p1, 0.f);
                    float s0 = a0 * a0, s1 = a1 * a1;
                    uint32_t u0 = __float_as_uint(s0), u1 = __float_as_uint(s1);
                    uint32_t hi = __byte_perm(u0, u1, 0x7632);
                    float l0 = s0 - __uint_as_float(u0 & 0xFFFF0000u);
                    float l1 = s1 - __uint_as_float(u1 & 0xFFFF0000u);
                    uint32_t lo;
                    asm("cvt.rn.satfinite.bf16x2.f32 %0, %1, %2;"
                        : "=r"(lo) : "f"(l1), "f"(l0));
                    *(uint32_t*)(Ohi + goff) = hi;
                    *(uint32_t*)(Olo + goff) = lo;
                } else {
                    float2 o;
                    if (EPI == 0) {
                        o = make_float2(p0, p1);
                    } else if (EPI == 2) {
                        float2 rs = *(const float2*)(Res + goff);
                        o = make_float2(rs.x + p0, rs.y + p1);
                    } else {
                        float2 rs = *(const float2*)(Res + goff);
                        float2 ax = *(const float2*)(Aux + goff);
                        o.x = rs.x + ax.x / (1.f + __expf(-p0));
                        o.y = rs.y + ax.y / (1.f + __expf(-p1));
                    }
                    *(float2*)(C + goff) = o;
                }
            }
        }
    }
}

// ---------------- weight split: fp32 -> bf16 hi/lo planes --------------------
__global__ void __launch_bounds__(256) wsplit_kernel(const float* __restrict__ w,
                                                     ushort16* __restrict__ hi,
                                                     ushort16* __restrict__ lo,
                                                     int n4) {
    const int i4 = blockIdx.x * 256 + threadIdx.x;
    if (i4 >= n4) return;
    float4 a = ((const float4*)w)[i4];
    uint32_t u0 = __float_as_uint(a.x), u1 = __float_as_uint(a.y);
    uint32_t u2 = __float_as_uint(a.z), u3 = __float_as_uint(a.w);
    uint2 h;
    h.x = __byte_perm(u0, u1, 0x7632);
    h.y = __byte_perm(u2, u3, 0x7632);
    float l0 = a.x - __uint_as_float(u0 & 0xFFFF0000u);
    float l1 = a.y - __uint_as_float(u1 & 0xFFFF0000u);
    float l2 = a.z - __uint_as_float(u2 & 0xFFFF0000u);
    float l3 = a.w - __uint_as_float(u3 & 0xFFFF0000u);
    uint2 l;
    asm("cvt.rn.satfinite.bf16x2.f32 %0, %1, %2;" : "=r"(l.x) : "f"(l1), "f"(l0));
    asm("cvt.rn.satfinite.bf16x2.f32 %0, %1, %2;" : "=r"(l.y) : "f"(l3), "f"(l2));
    ((uint2*)hi)[i4] = h;
    ((uint2*)lo)[i4] = l;
}

// ---------------- LayerNorm: one block per token row -------------------------
__global__ void __launch_bounds__(256) ln_kernel(const float* __restrict__ x,
                                                 const float* __restrict__ w,
                                                 const float* __restrict__ b,
                                                 float* __restrict__ out) {
    __shared__ float red[16];
    const int row = blockIdx.x;
    const int tid = threadIdx.x;
    const float4* xr = (const float4*)(x + (size_t)row * CDIM);
    float4 v = xr[tid];
    float s = v.x + v.y + v.z + v.w;
    float q = v.x*v.x + v.y*v.y + v.z*v.z + v.w*v.w;
    #pragma unroll
    for (int o = 16; o > 0; o >>= 1) {
        s += __shfl_xor_sync(0xffffffffu, s, o);
        q += __shfl_xor_sync(0xffffffffu, q, o);
    }
    const int lane = tid & 31, wd = tid >> 5;
    if (lane == 0) { red[wd] = s; red[8 + wd] = q; }
    __syncthreads();
    if (tid == 0) {
        float S = 0.f, Q = 0.f;
        #pragma unroll
        for (int i = 0; i < 8; i++) { S += red[i]; Q += red[8 + i]; }
        red[0] = S; red[8] = Q;
    }
    __syncthreads();
    const float mean = red[0] * (1.f / CDIM);
    const float var  = red[8] * (1.f / CDIM) - mean * mean;
    const float rstd = rsqrtf(var + 1e-5f);
    float4 w4 = ((const float4*)w)[tid];
    float4 b4 = ((const float4*)b)[tid];
    float4 o;
    o.x = (v.x - mean) * rstd * w4.x + b4.x;
    o.y = (v.y - mean) * rstd * w4.y + b4.y;
    o.z = (v.z - mean) * rstd * w4.z + b4.z;
    o.w = (v.w - mean) * rstd * w4.w + b4.w;
    ((float4*)(out + (size_t)row * CDIM))[tid] = o;
}

// ---------------- token-shift mixing (3 outputs, bf16 hi/lo planes) ----------
__global__ void __launch_bounds__(256) mix3_kernel(const float* __restrict__ h,
        const float* __restrict__ tk, const float* __restrict__ tv,
        const float* __restrict__ tr,
        ushort16* __restrict__ xkh, ushort16* __restrict__ xkl,
        ushort16* __restrict__ xvh, ushort16* __restrict__ xvl,
        ushort16* __restrict__ xrh, ushort16* __restrict__ xrl) {
    const size_t idx = (size_t)blockIdx.x * 256 + threadIdx.x;
    const int c = (int)(idx & (CDIM - 1));
    const int t = (int)((idx >> 10) & (TLEN - 1));
    const float hv = h[idx];
    const float pv = (t == 0) ? 0.f : h[idx - CDIM];
    const float d = hv - pv;
    split_store(xkh, xkl, idx, fmaf(tk[c], d, pv));
    split_store(xvh, xvl, idx, fmaf(tv[c], d, pv));
    split_store(xrh, xrl, idx, fmaf(tr[c], d, pv));
}

// ---------------- token-shift mixing (2 outputs, bf16 hi/lo planes) ----------
__global__ void __launch_bounds__(256) mix2_kernel(const float* __restrict__ h,
        const float* __restrict__ tk, const float* __restrict__ tr,
        ushort16* __restrict__ xkh, ushort16* __restrict__ xkl,
        ushort16* __restrict__ xrh, ushort16* __restrict__ xrl) {
    const size_t idx = (size_t)blockIdx.x * 256 + threadIdx.x;
    const int c = (int)(idx & (CDIM - 1));
    const int t = (int)((idx >> 10) & (TLEN - 1));
    const float hv = h[idx];
    const float pv = (t == 0) ? 0.f : h[idx - CDIM];
    const float d = hv - pv;
    split_store(xkh, xkl, idx, fmaf(tk[c], d, pv));
    split_store(xrh, xrl, idx, fmaf(tr[c], d, pv));
}

// ---------------- WKV recurrence, software-pipelined (depth 8) ---------------
__global__ void __launch_bounds__(64) wkv_kernel(const float* __restrict__ td,
                                                 const float* __restrict__ tf,
                                                 const float* __restrict__ k,
                                                 const float* __restrict__ v,
                                                 const float* __restrict__ r,
                                                 ushort16* __restrict__ yh,
                                                 ushort16* __restrict__ yl) {
    const int gid = blockIdx.x * 64 + threadIdx.x;     // < NB*CDIM
    const int c = gid & (CDIM - 1);
    const int b = gid >> 10;
    const float w = -__expf(td[c]);
    const float u = tf[c];
    float aa = 0.f, bb = 0.f, pp = -1e38f;
    const size_t base = (size_t)b * TLEN * CDIM + c;

    const int P = 8;
    float kp[P], vp[P], rp[P];
    #pragma unroll
    for (int j = 0; j < P; j++) {
        const size_t i = base + (size_t)j * CDIM;
        kp[j] = k[i]; vp[j] = v[i]; rp[j] = r[i];
    }

    for (int t0 = 0; t0 < TLEN; t0 += P) {
        const bool more = (t0 + P) < TLEN;
        #pragma unroll
        for (int j = 0; j < P; j++) {
            const size_t i = base + (size_t)(t0 + j) * CDIM;
            const float kt = kp[j], vt = vp[j], rr = rp[j];
            if (more) {
                const size_t ip = i + (size_t)P * CDIM;
                kp[j] = k[ip]; vp[j] = v[ip]; rp[j] = r[ip];
            }
            const float ww = u + kt;
            const float qq = fmaxf(pp, ww);
            const float e1 = __expf(pp - qq);
            const float e2 = __expf(ww - qq);
            const float yt = (e1 * aa + e2 * vt) / (e1 * bb + e2);
            const float yo = yt / (1.f + __expf(-rr));
            const uint32_t uy = __float_as_uint(yo);
            yh[i] = (ushort16)(uy >> 16);
            const float lo = yo - __uint_as_float(uy & 0xFFFF0000u);
            __nv_bfloat16 bl = __float2bfloat16(lo);
            yl[i] = *reinterpret_cast<ushort16*>(&bl);
            const float w2 = pp + w;
            const float q2 = fmaxf(w2, kt);
            const float e1b = __expf(w2 - q2);
            const float e2b = __expf(kt - q2);
            aa = e1b * aa + e2b * vt;
            bb = e1b * bb + e2b;
            pp = q2;
        }
    }
}

// ---------------- host orchestration ----------------------------------------
extern "C" void kernel_launch(void* const* d_in, const int* in_sizes, int n_in,
                              void* d_out, int out_size) {
    const float* x     = (const float*)d_in[0];
    const float* ln1w  = (const float*)d_in[1];
    const float* ln1b  = (const float*)d_in[2];
    const float* ln2w  = (const float*)d_in[3];
    const float* ln2b  = (const float*)d_in[4];
    const float* atmk  = (const float*)d_in[5];
    const float* atmv  = (const float*)d_in[6];
    const float* atmr  = (const float*)d_in[7];
    const float* tdec  = (const float*)d_in[8];
    const float* tfst  = (const float*)d_in[9];
    const float* Wk    = (const float*)d_in[10];
    const float* Wv    = (const float*)d_in[11];
    const float* Wr    = (const float*)d_in[12];
    const float* Wo    = (const float*)d_in[13];
    const float* ftmk  = (const float*)d_in[14];
    const float* ftmr  = (const float*)d_in[15];
    const float* Wkey  = (const float*)d_in[16];
    const float* Wrec  = (const float*)d_in[17];
    const float* Wval  = (const float*)d_in[18];
    float* out = (float*)d_out;

    float *h, *kb, *vb, *rb, *kvb;
    ushort16 *xkh, *xkl, *xvh, *xvl, *xrh, *xrl, *yh, *yl, *kkh, *kkl, *wh, *wl;
    cudaGetSymbolAddress((void**)&h,   g_h);
    cudaGetSymbolAddress((void**)&kb,  g_k);
    cudaGetSymbolAddress((void**)&vb,  g_v);
    cudaGetSymbolAddress((void**)&rb,  g_r);
    cudaGetSymbolAddress((void**)&kvb, g_kv);
    cudaGetSymbolAddress((void**)&xkh, g_xk_h); cudaGetSymbolAddress((void**)&xkl, g_xk_l);
    cudaGetSymbolAddress((void**)&xvh, g_xv_h); cudaGetSymbolAddress((void**)&xvl, g_xv_l);
    cudaGetSymbolAddress((void**)&xrh, g_xr_h); cudaGetSymbolAddress((void**)&xrl, g_xr_l);
    cudaGetSymbolAddress((void**)&yh,  g_y_h);  cudaGetSymbolAddress((void**)&yl,  g_y_l);
    cudaGetSymbolAddress((void**)&kkh, g_kk_h); cudaGetSymbolAddress((void**)&kkl, g_kk_l);
    cudaGetSymbolAddress((void**)&wh,  g_w_h);  cudaGetSymbolAddress((void**)&wl,  g_w_l);

    cudaFuncSetAttribute(hmma_gemm_kernel<0>, cudaFuncAttributeMaxDynamicSharedMemorySize, GEMM_SMEM_BYTES);
    cudaFuncSetAttribute(hmma_gemm_kernel<1>, cudaFuncAttributeMaxDynamicSharedMemorySize, GEMM_SMEM_BYTES);
    cudaFuncSetAttribute(hmma_gemm_kernel<2>, cudaFuncAttributeMaxDynamicSharedMemorySize, GEMM_SMEM_BYTES);
    cudaFuncSetAttribute(hmma_gemm_kernel<3>, cudaFuncAttributeMaxDynamicSharedMemorySize, GEMM_SMEM_BYTES);

    // weight plane offsets (elements)
    const size_t OW_K = 0,        OW_V = 1048576,  OW_R = 2097152,
                 OW_O = 3145728,  OW_REC = 4194304,
                 OW_KEY = 5242880, OW_VAL = 9437184;
    const int CC4 = (CDIM * CDIM) / 4;          // 262144
    const int CF4 = (CDIM * FDIM) / 4;          // 1048576

    // one-shot weight splits (cheap; rerun every call for determinism)
    wsplit_kernel<<<CC4 / 256, 256>>>(Wk,   wh + OW_K,   wl + OW_K,   CC4);
    wsplit_kernel<<<CC4 / 256, 256>>>(Wv,   wh + OW_V,   wl + OW_V,   CC4);
    wsplit_kernel<<<CC4 / 256, 256>>>(Wr,   wh + OW_R,   wl + OW_R,   CC4);
    wsplit_kernel<<<CC4 / 256, 256>>>(Wo,   wh + OW_O,   wl + OW_O,   CC4);
    wsplit_kernel<<<CC4 / 256, 256>>>(Wrec, wh + OW_REC, wl + OW_REC, CC4);
    wsplit_kernel<<<CF4 / 256, 256>>>(Wkey, wh + OW_KEY, wl + OW_KEY, CF4);
    wsplit_kernel<<<CF4 / 256, 256>>>(Wval, wh + OW_VAL, wl + OW_VAL, CF4);

    const int elemBlocks = (BT * CDIM) / 256;    // 65536
    const dim3 gC(CDIM / 128, BT / 128);         // (8, 128)
    const dim3 gF(FDIM / 128, BT / 128);         // (32, 128)

    // ---- attention half ----
    ln_kernel<<<BT, 256>>>(x, ln1w, ln1b, h);
    mix3_kernel<<<elemBlocks, 256>>>(h, atmk, atmv, atmr, xkh, xkl, xvh, xvl, xrh, xrl);
    hmma_gemm_kernel<0><<<gC, 256, GEMM_SMEM_BYTES>>>(BT, CDIM, CDIM,
        xkh, xkl, wh + OW_K, wl + OW_K, kb, nullptr, nullptr, nullptr, nullptr);
    hmma_gemm_kernel<0><<<gC, 256, GEMM_SMEM_BYTES>>>(BT, CDIM, CDIM,
        xvh, xvl, wh + OW_V, wl + OW_V, vb, nullptr, nullptr, nullptr, nullptr);
    hmma_gemm_kernel<0><<<gC, 256, GEMM_SMEM_BYTES>>>(BT, CDIM, CDIM,
        xrh, xrl, wh + OW_R, wl + OW_R, rb, nullptr, nullptr, nullptr, nullptr);
    wkv_kernel<<<(NB * CDIM) / 64, 64>>>(tdec, tfst, kb, vb, rb, yh, yl);
    hmma_gemm_kernel<2><<<gC, 256, GEMM_SMEM_BYTES>>>(BT, CDIM, CDIM,
        yh, yl, wh + OW_O, wl + OW_O, out, nullptr, nullptr, x, nullptr);

    // ---- FFN half ----
    ln_kernel<<<BT, 256>>>(out, ln2w, ln2b, h);
    mix2_kernel<<<elemBlocks, 256>>>(h, ftmk, ftmr, xkh, xkl, xrh, xrl);
    hmma_gemm_kernel<1><<<gF, 256, GEMM_SMEM_BYTES>>>(BT, FDIM, CDIM,
        xkh, xkl, wh + OW_KEY, wl + OW_KEY, nullptr, kkh, kkl, nullptr, nullptr);
    hmma_gemm_kernel<0><<<gC, 256, GEMM_SMEM_BYTES>>>(BT, CDIM, FDIM,
        kkh, kkl, wh + OW_VAL, wl + OW_VAL, kvb, nullptr, nullptr, nullptr, nullptr);
    hmma_gemm_kernel<3><<<gC, 256, GEMM_SMEM_BYTES>>>(BT, CDIM, CDIM,
        xrh, xrl, wh + OW_REC, wl + OW_REC, out, nullptr, nullptr, out, kvb);
}

// round 11
// speedup vs baseline: 2.3178x; 1.0012x over previous
#include <cuda_runtime.h>
#include <cuda_bf16.h>
#include <cstdint>
#include <cstddef>

// ---------------- problem constants ----------------
#define NB    8
#define TLEN  2048
#define CDIM  1024
#define FDIM  4096
#define BT    (NB * TLEN)        // 16384 tokens

typedef unsigned short ushort16;

// ---------------- scratch (static device globals; no allocations allowed) ----
__device__ float g_h [BT * CDIM];
__device__ float g_k [BT * CDIM];
__device__ float g_v [BT * CDIM];
__device__ float g_r [BT * CDIM];
__device__ float g_kv[BT * CDIM];
__device__ ushort16 g_xk_h[BT * CDIM], g_xk_l[BT * CDIM];
__device__ ushort16 g_xv_h[BT * CDIM], g_xv_l[BT * CDIM];
__device__ ushort16 g_xr_h[BT * CDIM], g_xr_l[BT * CDIM];
__device__ ushort16 g_y_h [BT * CDIM], g_y_l [BT * CDIM];
__device__ ushort16 g_kk_h[(size_t)BT * FDIM], g_kk_l[(size_t)BT * FDIM];
__device__ ushort16 g_w_h[13631488], g_w_l[13631488];   // 13M weight elems

// ============================================================================
// helpers
// ============================================================================
__device__ __forceinline__ uint32_t smem_u32(const void* p) {
    uint32_t a;
    asm("{ .reg .u64 t; cvta.to.shared.u64 t, %1; cvt.u32.u64 %0, t; }"
        : "=r"(a) : "l"(p));
    return a;
}
__device__ __forceinline__ void ldsm_x4(uint32_t* r, uint32_t addr) {
    asm volatile("ldmatrix.sync.aligned.m8n8.x4.shared.b16 {%0,%1,%2,%3}, [%4];"
        : "=r"(r[0]), "=r"(r[1]), "=r"(r[2]), "=r"(r[3]) : "r"(addr));
}
__device__ __forceinline__ void mma16816(float* d, const uint32_t* a,
                                         uint32_t b0, uint32_t b1) {
    asm volatile("mma.sync.aligned.m16n8k16.row.col.f32.bf16.bf16.f32 "
        "{%0,%1,%2,%3}, {%4,%5,%6,%7}, {%8,%9}, {%0,%1,%2,%3};"
        : "+f"(d[0]), "+f"(d[1]), "+f"(d[2]), "+f"(d[3])
        : "r"(a[0]), "r"(a[1]), "r"(a[2]), "r"(a[3]), "r"(b0), "r"(b1));
}
__device__ __forceinline__ void split_store(ushort16* __restrict__ hp,
                                            ushort16* __restrict__ lp,
                                            size_t i, float x) {
    const uint32_t u = __float_as_uint(x);
    hp[i] = (ushort16)(u >> 16);
    const float lo = x - __uint_as_float(u & 0xFFFF0000u);
    __nv_bfloat16 b = __float2bfloat16(lo);
    lp[i] = *reinterpret_cast<ushort16*>(&b);
}

// ============================================================================
// HMMA GEMM: C[M,N] = A[M,K] @ B[N,K]^T  from pre-split bf16 hi/lo planes.
// BM=128, BN=128, BK=32; 8 warps 4(m) x 2(n); 4-stage cp.async pipeline.
// Pass-major MMA schedule: same-accumulator reuse distance = 16 MMAs (hides
// HMMA RAW latency at low occupancy).
// EPI 0: C=acc  1: {Ohi,Olo}=split(relu(acc)^2)  2: C=Res+acc
// EPI 3: C=Res+sigmoid(acc)*Aux
// ============================================================================
#define ROWB        80               // 32 bf16 (64B) + 16B pad per SMEM row
#define PLANE_BYTES 10240            // 128 * 80
#define STG_BYTES   40960            // 4 planes (A_hi, A_lo, B_hi, B_lo)
#define NSTAGE      4
#define GEMM_SMEM_BYTES (NSTAGE * STG_BYTES)   // 163840

template <int EPI>
__global__ void __launch_bounds__(256, 1) hmma_gemm_kernel(
    int M, int N, int K,
    const ushort16* __restrict__ Ah, const ushort16* __restrict__ Al,
    const ushort16* __restrict__ Bh, const ushort16* __restrict__ Bl,
    float* __restrict__ C,
    ushort16* __restrict__ Ohi, ushort16* __restrict__ Olo,
    const float* __restrict__ Res,
    const float* __restrict__ Aux)
{
    extern __shared__ __align__(128) char dynsmem[];
    const uint32_t sm = smem_u32(dynsmem);
    const int tid = threadIdx.x;
    const int wid = tid >> 5, lid = tid & 31;
    const int wm = wid >> 1, wn = wid & 1;

    const ushort16* gp0 = Ah + (size_t)(blockIdx.y * 128) * K;
    const ushort16* gp1 = Al + (size_t)(blockIdx.y * 128) * K;
    const ushort16* gp2 = Bh + (size_t)(blockIdx.x * 128) * K;
    const ushort16* gp3 = Bl + (size_t)(blockIdx.x * 128) * K;

    float acc[2][8][4];
    #pragma unroll
    for (int f = 0; f < 2; f++)
        #pragma unroll
        for (int j = 0; j < 8; j++)
            #pragma unroll
            for (int c = 0; c < 4; c++) acc[f][j][c] = 0.f;

    const int ns = K >> 5;           // K / 32

    // cp.async fill of one stage: 4 planes x 128 rows x 64B = 2048 x 16B chunks
    auto issue = [&](int s) {
        const uint32_t base = sm + (s & 3) * STG_BYTES;
        #pragma unroll
        for (int i = 0; i < 8; i++) {
            const int plane = i >> 1;
            const int idx2 = ((i & 1) << 8) | tid;     // 0..511 within plane
            const int row = idx2 >> 2;
            const int kq  = idx2 & 3;                  // 16B chunk in k-row
            const ushort16* src =
                (plane == 0 ? gp0 : plane == 1 ? gp1 : plane == 2 ? gp2 : gp3)
                + (size_t)row * K + s * 32 + kq * 8;
            const uint32_t dst = base + plane * PLANE_BYTES + row * ROWB + kq * 16;
            asm volatile("cp.async.cg.shared.global [%0], [%1], 16;"
                         :: "r"(dst), "l"(src) : "memory");
        }
        asm volatile("cp.async.commit_group;" ::: "memory");
    };

    issue(0); issue(1); issue(2);

    const uint32_t lrow16 = (lid & 15);
    const uint32_t lhi16  = (lid >> 4) * 16;           // +16B for k8..15 mats

    for (int s = 0; s < ns; s++) {
        asm volatile("cp.async.wait_group 2;" ::: "memory");
        __syncthreads();
        if (s + 3 < ns) issue(s + 3);

        const uint32_t base = sm + (s & 3) * STG_BYTES;
        #pragma unroll
        for (int ks = 0; ks < 2; ks++) {
            const uint32_t kb = ks * 32 + lhi16;
            uint32_t ah[2][4], al[2][4], bh[4][4], bl[4][4];
            const uint32_t arow = wm * 32 + lrow16;
            ldsm_x4(ah[0], base + 0 * PLANE_BYTES + arow * ROWB + kb);
            ldsm_x4(ah[1], base + 0 * PLANE_BYTES + (arow + 16) * ROWB + kb);
            ldsm_x4(al[0], base + 1 * PLANE_BYTES + arow * ROWB + kb);
            ldsm_x4(al[1], base + 1 * PLANE_BYTES + (arow + 16) * ROWB + kb);
            const uint32_t brow = wn * 64 + lrow16;
            #pragma unroll
            for (int nb = 0; nb < 4; nb++) {
                ldsm_x4(bh[nb], base + 2 * PLANE_BYTES + (brow + nb * 16) * ROWB + kb);
                ldsm_x4(bl[nb], base + 3 * PLANE_BYTES + (brow + nb * 16) * ROWB + kb);
            }
            // -------- pass-major schedule: 16 independent MMAs per pass -----
            #pragma unroll
            for (int f = 0; f < 2; f++)                 // pass 1: hi * hi
                #pragma unroll
                for (int j = 0; j < 8; j++) {
                    const int nb = j >> 1, sl = j & 1;
                    mma16816(acc[f][j], ah[f], bh[nb][sl], bh[nb][sl + 2]);
                }
            #pragma unroll
            for (int f = 0; f < 2; f++)                 // pass 2: hi * lo
                #pragma unroll
                for (int j = 0; j < 8; j++) {
                    const int nb = j >> 1, sl = j & 1;
                    mma16816(acc[f][j], ah[f], bl[nb][sl], bl[nb][sl + 2]);
                }
            #pragma unroll
            for (int f = 0; f < 2; f++)                 // pass 3: lo * hi
                #pragma unroll
                for (int j = 0; j < 8; j++) {
                    const int nb = j >> 1, sl = j & 1;
                    mma16816(acc[f][j], al[f], bh[nb][sl], bh[nb][sl + 2]);
                }
        }
    }

    // ---- epilogue: direct register -> global, fused ----
    const int r0 = lid >> 2;
    const int c0 = (lid & 3) * 2;
    #pragma unroll
    for (int f = 0; f < 2; f++) {
        #pragma unroll
        for (int j = 0; j < 8; j++) {
            const int row = blockIdx.y * 128 + wm * 32 + f * 16 + r0;
            const int col = blockIdx.x * 128 + wn * 64 + j * 8 + c0;
            #pragma unroll
            for (int hh = 0; hh < 2; hh++) {
                const size_t goff = (size_t)(row + hh * 8) * N + col;
                float p0 = acc[f][j][hh * 2 + 0];
                float p1 = acc[f][j][hh * 2 + 1];
                if (EPI == 1) {
                    float a0 = fmaxf(p0, 0.f), a1 = fmaxf(p1, 0.f);
                    float s0 = a0 * a0, s1 = a1 * a1;
                    uint32_t u0 = __float_as_uint(s0), u1 = __float_as_uint(s1);
                    uint32_t hi = __byte_perm(u0, u1, 0x7632);
                    float l0 = s0 - __uint_as_float(u0 & 0xFFFF0000u);
                    float l1 = s1 - __uint_as_float(u1 & 0xFFFF0000u);
                    uint32_t lo;
                    asm("cvt.rn.satfinite.bf16x2.f32 %0, %1, %2;"
                        : "=r"(lo) : "f"(l1), "f"(l0));
                    *(uint32_t*)(Ohi + goff) = hi;
                    *(uint32_t*)(Olo + goff) = lo;
                } else {
                    float2 o;
                    if (EPI == 0) {
                        o = make_float2(p0, p1);
                    } else if (EPI == 2) {
                        float2 rs = *(const float2*)(Res + goff);
                        o = make_float2(rs.x + p0, rs.y + p1);
                    } else {
                        float2 rs = *(const float2*)(Res + goff);
                        float2 ax = *(const float2*)(Aux + goff);
                        o.x = rs.x + ax.x / (1.f + __expf(-p0));
                        o.y = rs.y + ax.y / (1.f + __expf(-p1));
                    }
                    *(float2*)(C + goff) = o;
                }
            }
        }
    }
}

// ---------------- weight split: fp32 -> bf16 hi/lo planes --------------------
__global__ void __launch_bounds__(256) wsplit_kernel(const float* __restrict__ w,
                                                     ushort16* __restrict__ hi,
                                                     ushort16* __restrict__ lo,
                                                     int n4) {
    const int i4 = blockIdx.x * 256 + threadIdx.x;
    if (i4 >= n4) return;
    float4 a = ((const float4*)w)[i4];
    uint32_t u0 = __float_as_uint(a.x), u1 = __float_as_uint(a.y);
    uint32_t u2 = __float_as_uint(a.z), u3 = __float_as_uint(a.w);
    uint2 h;
    h.x = __byte_perm(u0, u1, 0x7632);
    h.y = __byte_perm(u2, u3, 0x7632);
    float l0 = a.x - __uint_as_float(u0 & 0xFFFF0000u);
    float l1 = a.y - __uint_as_float(u1 & 0xFFFF0000u);
    float l2 = a.z - __uint_as_float(u2 & 0xFFFF0000u);
    float l3 = a.w - __uint_as_float(u3 & 0xFFFF0000u);
    uint2 l;
    asm("cvt.rn.satfinite.bf16x2.f32 %0, %1, %2;" : "=r"(l.x) : "f"(l1), "f"(l0));
    asm("cvt.rn.satfinite.bf16x2.f32 %0, %1, %2;" : "=r"(l.y) : "f"(l3), "f"(l2));
    ((uint2*)hi)[i4] = h;
    ((uint2*)lo)[i4] = l;
}

// ---------------- LayerNorm: one block per token row -------------------------
__global__ void __launch_bounds__(256) ln_kernel(const float* __restrict__ x,
                                                 const float* __restrict__ w,
                                                 const float* __restrict__ b,
                                                 float* __restrict__ out) {
    __shared__ float red[16];
    const int row = blockIdx.x;
    const int tid = threadIdx.x;
    const float4* xr = (const float4*)(x + (size_t)row * CDIM);
    float4 v = xr[tid];
    float s = v.x + v.y + v.z + v.w;
    float q = v.x*v.x + v.y*v.y + v.z*v.z + v.w*v.w;
    #pragma unroll
    for (int o = 16; o > 0; o >>= 1) {
        s += __shfl_xor_sync(0xffffffffu, s, o);
        q += __shfl_xor_sync(0xffffffffu, q, o);
    }
    const int lane = tid & 31, wd = tid >> 5;
    if (lane == 0) { red[wd] = s; red[8 + wd] = q; }
    __syncthreads();
    if (tid == 0) {
        float S = 0.f, Q = 0.f;
        #pragma unroll
        for (int i = 0; i < 8; i++) { S += red[i]; Q += red[8 + i]; }
        red[0] = S; red[8] = Q;
    }
    __syncthreads();
    const float mean = red[0] * (1.f / CDIM);
    const float var  = red[8] * (1.f / CDIM) - mean * mean;
    const float rstd = rsqrtf(var + 1e-5f);
    float4 w4 = ((const float4*)w)[tid];
    float4 b4 = ((const float4*)b)[tid];
    float4 o;
    o.x = (v.x - mean) * rstd * w4.x + b4.x;
    o.y = (v.y - mean) * rstd * w4.y + b4.y;
    o.z = (v.z - mean) * rstd * w4.z + b4.z;
    o.w = (v.w - mean) * rstd * w4.w + b4.w;
    ((float4*)(out + (size_t)row * CDIM))[tid] = o;
}

// ---------------- token-shift mixing (3 outputs, bf16 hi/lo planes) ----------
__global__ void __launch_bounds__(256) mix3_kernel(const float* __restrict__ h,
        const float* __restrict__ tk, const float* __restrict__ tv,
        const float* __restrict__ tr,
        ushort16* __restrict__ xkh, ushort16* __restrict__ xkl,
        ushort16* __restrict__ xvh, ushort16* __restrict__ xvl,
        ushort16* __restrict__ xrh, ushort16* __restrict__ xrl) {
    const size_t idx = (size_t)blockIdx.x * 256 + threadIdx.x;
    const int c = (int)(idx & (CDIM - 1));
    const int t = (int)((idx >> 10) & (TLEN - 1));
    const float hv = h[idx];
    const float pv = (t == 0) ? 0.f : h[idx - CDIM];
    const float d = hv - pv;
    split_store(xkh, xkl, idx, fmaf(tk[c], d, pv));
    split_store(xvh, xvl, idx, fmaf(tv[c], d, pv));
    split_store(xrh, xrl, idx, fmaf(tr[c], d, pv));
}

// ---------------- token-shift mixing (2 outputs, bf16 hi/lo planes) ----------
__global__ void __launch_bounds__(256) mix2_kernel(const float* __restrict__ h,
        const float* __restrict__ tk, const float* __restrict__ tr,
        ushort16* __restrict__ xkh, ushort16* __restrict__ xkl,
        ushort16* __restrict__ xrh, ushort16* __restrict__ xrl) {
    const size_t idx = (size_t)blockIdx.x * 256 + threadIdx.x;
    const int c = (int)(idx & (CDIM - 1));
    const int t = (int)((idx >> 10) & (TLEN - 1));
    const float hv = h[idx];
    const float pv = (t == 0) ? 0.f : h[idx - CDIM];
    const float d = hv - pv;
    split_store(xkh, xkl, idx, fmaf(tk[c], d, pv));
    split_store(xrh, xrl, idx, fmaf(tr[c], d, pv));
}

// ---------------- WKV recurrence, software-pipelined (depth 8) ---------------
__global__ void __launch_bounds__(64) wkv_kernel(const float* __restrict__ td,
                                                 const float* __restrict__ tf,
                                                 const float* __restrict__ k,
                                                 const float* __restrict__ v,
                                                 const float* __restrict__ r,
                                                 ushort16* __restrict__ yh,
                                                 ushort16* __restrict__ yl) {
    const int gid = blockIdx.x * 64 + threadIdx.x;     // < NB*CDIM
    const int c = gid & (CDIM - 1);
    const int b = gid >> 10;
    const float w = -__expf(td[c]);
    const float u = tf[c];
    float aa = 0.f, bb = 0.f, pp = -1e38f;
    const size_t base = (size_t)b * TLEN * CDIM + c;

    const int P = 8;
    float kp[P], vp[P], rp[P];
    #pragma unroll
    for (int j = 0; j < P; j++) {
        const size_t i = base + (size_t)j * CDIM;
        kp[j] = k[i]; vp[j] = v[i]; rp[j] = r[i];
    }

    for (int t0 = 0; t0 < TLEN; t0 += P) {
        const bool more = (t0 + P) < TLEN;
        #pragma unroll
        for (int j = 0; j < P; j++) {
            const size_t i = base + (size_t)(t0 + j) * CDIM;
            const float kt = kp[j], vt = vp[j], rr = rp[j];
            if (more) {
                const size_t ip = i + (size_t)P * CDIM;
                kp[j] = k[ip]; vp[j] = v[ip]; rp[j] = r[ip];
            }
            const float ww = u + kt;
            const float qq = fmaxf(pp, ww);
            const float e1 = __expf(pp - qq);
            const float e2 = __expf(ww - qq);
            const float yt = (e1 * aa + e2 * vt) / (e1 * bb + e2);
            const float yo = yt / (1.f + __expf(-rr));
            const uint32_t uy = __float_as_uint(yo);
            yh[i] = (ushort16)(uy >> 16);
            const float lo = yo - __uint_as_float(uy & 0xFFFF0000u);
            __nv_bfloat16 bl = __float2bfloat16(lo);
            yl[i] = *reinterpret_cast<ushort16*>(&bl);
            const float w2 = pp + w;
            const float q2 = fmaxf(w2, kt);
            const float e1b = __expf(w2 - q2);
            const float e2b = __expf(kt - q2);
            aa = e1b * aa + e2b * vt;
            bb = e1b * bb + e2b;
            pp = q2;
        }
    }
}

// ---------------- host orchestration ----------------------------------------
extern "C" void kernel_launch(void* const* d_in, const int* in_sizes, int n_in,
                              void* d_out, int out_size) {
    const float* x     = (const float*)d_in[0];
    const float* ln1w  = (const float*)d_in[1];
    const float* ln1b  = (const float*)d_in[2];
    const float* ln2w  = (const float*)d_in[3];
    const float* ln2b  = (const float*)d_in[4];
    const float* atmk  = (const float*)d_in[5];
    const float* atmv  = (const float*)d_in[6];
    const float* atmr  = (const float*)d_in[7];
    const float* tdec  = (const float*)d_in[8];
    const float* tfst  = (const float*)d_in[9];
    const float* Wk    = (const float*)d_in[10];
    const float* Wv    = (const float*)d_in[11];
    const float* Wr    = (const float*)d_in[12];
    const float* Wo    = (const float*)d_in[13];
    const float* ftmk  = (const float*)d_in[14];
    const float* ftmr  = (const float*)d_in[15];
    const float* Wkey  = (const float*)d_in[16];
    const float* Wrec  = (const float*)d_in[17];
    const float* Wval  = (const float*)d_in[18];
    float* out = (float*)d_out;

    float *h, *kb, *vb, *rb, *kvb;
    ushort16 *xkh, *xkl, *xvh, *xvl, *xrh, *xrl, *yh, *yl, *kkh, *kkl, *wh, *wl;
    cudaGetSymbolAddress((void**)&h,   g_h);
    cudaGetSymbolAddress((void**)&kb,  g_k);
    cudaGetSymbolAddress((void**)&vb,  g_v);
    cudaGetSymbolAddress((void**)&rb,  g_r);
    cudaGetSymbolAddress((void**)&kvb, g_kv);
    cudaGetSymbolAddress((void**)&xkh, g_xk_h); cudaGetSymbolAddress((void**)&xkl, g_xk_l);
    cudaGetSymbolAddress((void**)&xvh, g_xv_h); cudaGetSymbolAddress((void**)&xvl, g_xv_l);
    cudaGetSymbolAddress((void**)&xrh, g_xr_h); cudaGetSymbolAddress((void**)&xrl, g_xr_l);
    cudaGetSymbolAddress((void**)&yh,  g_y_h);  cudaGetSymbolAddress((void**)&yl,  g_y_l);
    cudaGetSymbolAddress((void**)&kkh, g_kk_h); cudaGetSymbolAddress((void**)&kkl, g_kk_l);
    cudaGetSymbolAddress((void**)&wh,  g_w_h);  cudaGetSymbolAddress((void**)&wl,  g_w_l);

    cudaFuncSetAttribute(hmma_gemm_kernel<0>, cudaFuncAttributeMaxDynamicSharedMemorySize, GEMM_SMEM_BYTES);
    cudaFuncSetAttribute(hmma_gemm_kernel<1>, cudaFuncAttributeMaxDynamicSharedMemorySize, GEMM_SMEM_BYTES);
    cudaFuncSetAttribute(hmma_gemm_kernel<2>, cudaFuncAttributeMaxDynamicSharedMemorySize, GEMM_SMEM_BYTES);
    cudaFuncSetAttribute(hmma_gemm_kernel<3>, cudaFuncAttributeMaxDynamicSharedMemorySize, GEMM_SMEM_BYTES);

    // weight plane offsets (elements)
    const size_t OW_K = 0,        OW_V = 1048576,  OW_R = 2097152,
                 OW_O = 3145728,  OW_REC = 4194304,
                 OW_KEY = 5242880, OW_VAL = 9437184;
    const int CC4 = (CDIM * CDIM) / 4;          // 262144
    const int CF4 = (CDIM * FDIM) / 4;          // 1048576

    // one-shot weight splits (cheap; rerun every call for determinism)
    wsplit_kernel<<<CC4 / 256, 256>>>(Wk,   wh + OW_K,   wl + OW_K,   CC4);
    wsplit_kernel<<<CC4 / 256, 256>>>(Wv,   wh + OW_V,   wl + OW_V,   CC4);
    wsplit_kernel<<<CC4 / 256, 256>>>(Wr,   wh + OW_R,   wl + OW_R,   CC4);
    wsplit_kernel<<<CC4 / 256, 256>>>(Wo,   wh + OW_O,   wl + OW_O,   CC4);
    wsplit_kernel<<<CC4 / 256, 256>>>(Wrec, wh + OW_REC, wl + OW_REC, CC4);
    wsplit_kernel<<<CF4 / 256, 256>>>(Wkey, wh + OW_KEY, wl + OW_KEY, CF4);
    wsplit_kernel<<<CF4 / 256, 256>>>(Wval, wh + OW_VAL, wl + OW_VAL, CF4);

    const int elemBlocks = (BT * CDIM) / 256;    // 65536
    const dim3 gC(CDIM / 128, BT / 128);         // (8, 128)
    const dim3 gF(FDIM / 128, BT / 128);         // (32, 128)

    // ---- attention half ----
    ln_kernel<<<BT, 256>>>(x, ln1w, ln1b, h);
    mix3_kernel<<<elemBlocks, 256>>>(h, atmk, atmv, atmr, xkh, xkl, xvh, xvl, xrh, xrl);
    hmma_gemm_kernel<0><<<gC, 256, GEMM_SMEM_BYTES>>>(BT, CDIM, CDIM,
        xkh, xkl, wh + OW_K, wl + OW_K, kb, nullptr, nullptr, nullptr, nullptr);
    hmma_gemm_kernel<0><<<gC, 256, GEMM_SMEM_BYTES>>>(BT, CDIM, CDIM,
        xvh, xvl, wh + OW_V, wl + OW_V, vb, nullptr, nullptr, nullptr, nullptr);
    hmma_gemm_kernel<0><<<gC, 256, GEMM_SMEM_BYTES>>>(BT, CDIM, CDIM,
        xrh, xrl, wh + OW_R, wl + OW_R, rb, nullptr, nullptr, nullptr, nullptr);
    wkv_kernel<<<(NB * CDIM) / 64, 64>>>(tdec, tfst, kb, vb, rb, yh, yl);
    hmma_gemm_kernel<2><<<gC, 256, GEMM_SMEM_BYTES>>>(BT, CDIM, CDIM,
        yh, yl, wh + OW_O, wl + OW_O, out, nullptr, nullptr, x, nullptr);

    // ---- FFN half ----
    ln_kernel<<<BT, 256>>>(out, ln2w, ln2b, h);
    mix2_kernel<<<elemBlocks, 256>>>(h, ftmk, ftmr, xkh, xkl, xrh, xrl);
    hmma_gemm_kernel<1><<<gF, 256, GEMM_SMEM_BYTES>>>(BT, FDIM, CDIM,
        xkh, xkl, wh + OW_KEY, wl + OW_KEY, nullptr, kkh, kkl, nullptr, nullptr);
    hmma_gemm_kernel<0><<<gC, 256, GEMM_SMEM_BYTES>>>(BT, CDIM, FDIM,
        kkh, kkl, wh + OW_VAL, wl + OW_VAL, kvb, nullptr, nullptr, nullptr, nullptr);
    hmma_gemm_kernel<3><<<gC, 256, GEMM_SMEM_BYTES>>>(BT, CDIM, CDIM,
        xrh, xrl, wh + OW_REC, wl + OW_REC, out, nullptr, nullptr, out, kvb);
}

// round 12
// speedup vs baseline: 3.0479x; 1.3150x over previous
#include <cuda_runtime.h>
#include <cuda_bf16.h>
#include <cuda_fp16.h>
#include <cstdint>
#include <cstddef>

// ---------------- problem constants ----------------
#define NB    8
#define TLEN  2048
#define CDIM  1024
#define FDIM  4096
#define BT    (NB * TLEN)        // 16384 tokens

typedef unsigned short ushort16;

// ---------------- scratch (static device globals; no allocations allowed) ----
__device__ float g_h [BT * CDIM];
__device__ float g_k [BT * CDIM];
__device__ float g_v [BT * CDIM];
__device__ float g_r [BT * CDIM];
__device__ float g_kv[BT * CDIM];
__device__ ushort16 g_xk_h[BT * CDIM], g_xk_l[BT * CDIM];
__device__ ushort16 g_xv_h[BT * CDIM], g_xv_l[BT * CDIM];
__device__ ushort16 g_xr_h[BT * CDIM], g_xr_l[BT * CDIM];
__device__ ushort16 g_y_h [BT * CDIM], g_y_l [BT * CDIM];
__device__ ushort16 g_kk_h[(size_t)BT * FDIM], g_kk_l[(size_t)BT * FDIM];
__device__ ushort16 g_w_h[13631488];              // fp16 weights (all 7 mats)

// ============================================================================
// helpers
// ============================================================================
__device__ __forceinline__ uint32_t smem_u32(const void* p) {
    uint32_t a;
    asm("{ .reg .u64 t; cvta.to.shared.u64 t, %1; cvt.u32.u64 %0, t; }"
        : "=r"(a) : "l"(p));
    return a;
}
__device__ __forceinline__ void ldsm_x4(uint32_t* r, uint32_t addr) {
    asm volatile("ldmatrix.sync.aligned.m8n8.x4.shared.b16 {%0,%1,%2,%3}, [%4];"
        : "=r"(r[0]), "=r"(r[1]), "=r"(r[2]), "=r"(r[3]) : "r"(addr));
}
__device__ __forceinline__ void mma16816(float* d, const uint32_t* a,
                                         uint32_t b0, uint32_t b1) {
    asm volatile("mma.sync.aligned.m16n8k16.row.col.f32.f16.f16.f32 "
        "{%0,%1,%2,%3}, {%4,%5,%6,%7}, {%8,%9}, {%0,%1,%2,%3};"
        : "+f"(d[0]), "+f"(d[1]), "+f"(d[2]), "+f"(d[3])
        : "r"(a[0]), "r"(a[1]), "r"(a[2]), "r"(a[3]), "r"(b0), "r"(b1));
}
// fp16 hi/lo split store (hi = rn(x); lo = rn(x - hi), subtraction exact)
__device__ __forceinline__ void split_store(ushort16* __restrict__ hp,
                                            ushort16* __restrict__ lp,
                                            size_t i, float x) {
    __half h = __float2half_rn(x);
    hp[i] = __half_as_ushort(h);
    const float lo = x - __half2float(h);
    lp[i] = __half_as_ushort(__float2half_rn(lo));
}

// ============================================================================
// HMMA GEMM: C[M,N] = A[M,K] @ B[N,K]^T.  A in fp16 hi/lo planes, B in fp16.
// D = A_hi*B + A_lo*B (2 passes, fp32 accum).
// BM=128, BN=128, BK=32; 8 warps 4(m) x 2(n); 4-stage cp.async pipeline.
// EPI 0: C=acc  1: {Ohi,Olo}=split(relu(acc)^2)  2: C=Res+acc
// EPI 3: C=Res+sigmoid(acc)*Aux
// ============================================================================
#define ROWB        80               // 32 fp16 (64B) + 16B pad per SMEM row
#define PLANE_BYTES 10240            // 128 * 80
#define STG_BYTES   30720            // 3 planes (A_hi, A_lo, B)
#define NSTAGE      4
#define GEMM_SMEM_BYTES (NSTAGE * STG_BYTES)   // 122880

template <int EPI>
__global__ void __launch_bounds__(256, 1) hmma_gemm_kernel(
    int M, int N, int K,
    const ushort16* __restrict__ Ah, const ushort16* __restrict__ Al,
    const ushort16* __restrict__ Bw,
    float* __restrict__ C,
    ushort16* __restrict__ Ohi, ushort16* __restrict__ Olo,
    const float* __restrict__ Res,
    const float* __restrict__ Aux)
{
    extern __shared__ __align__(128) char dynsmem[];
    const uint32_t sm = smem_u32(dynsmem);
    const int tid = threadIdx.x;
    const int wid = tid >> 5, lid = tid & 31;
    const int wm = wid >> 1, wn = wid & 1;

    const ushort16* gp0 = Ah + (size_t)(blockIdx.y * 128) * K;
    const ushort16* gp1 = Al + (size_t)(blockIdx.y * 128) * K;
    const ushort16* gp2 = Bw + (size_t)(blockIdx.x * 128) * K;

    float acc[2][8][4];
    #pragma unroll
    for (int f = 0; f < 2; f++)
        #pragma unroll
        for (int j = 0; j < 8; j++)
            #pragma unroll
            for (int c = 0; c < 4; c++) acc[f][j][c] = 0.f;

    const int ns = K >> 5;           // K / 32

    // cp.async fill of one stage: 3 planes x 128 rows x 64B = 1536 x 16B chunks
    auto issue = [&](int s) {
        const uint32_t base = sm + (s & 3) * STG_BYTES;
        #pragma unroll
        for (int i = 0; i < 6; i++) {
            const int plane = i >> 1;
            const int idx2 = ((i & 1) << 8) | tid;     // 0..511 within plane
            const int row = idx2 >> 2;
            const int kq  = idx2 & 3;                  // 16B chunk in k-row
            const ushort16* src =
                (plane == 0 ? gp0 : plane == 1 ? gp1 : gp2)
                + (size_t)row * K + s * 32 + kq * 8;
            const uint32_t dst = base + plane * PLANE_BYTES + row * ROWB + kq * 16;
            asm volatile("cp.async.cg.shared.global [%0], [%1], 16;"
                         :: "r"(dst), "l"(src) : "memory");
        }
        asm volatile("cp.async.commit_group;" ::: "memory");
    };

    issue(0); issue(1); issue(2);

    const uint32_t lrow16 = (lid & 15);
    const uint32_t lhi16  = (lid >> 4) * 16;           // +16B for k8..15 mats

    for (int s = 0; s < ns; s++) {
        asm volatile("cp.async.wait_group 2;" ::: "memory");
        __syncthreads();
        if (s + 3 < ns) issue(s + 3);

        const uint32_t base = sm + (s & 3) * STG_BYTES;
        #pragma unroll
        for (int ks = 0; ks < 2; ks++) {
            const uint32_t kb = ks * 32 + lhi16;
            uint32_t ah[2][4], al[2][4], bw[4][4];
            const uint32_t arow = wm * 32 + lrow16;
            ldsm_x4(ah[0], base + 0 * PLANE_BYTES + arow * ROWB + kb);
            ldsm_x4(ah[1], base + 0 * PLANE_BYTES + (arow + 16) * ROWB + kb);
            ldsm_x4(al[0], base + 1 * PLANE_BYTES + arow * ROWB + kb);
            ldsm_x4(al[1], base + 1 * PLANE_BYTES + (arow + 16) * ROWB + kb);
            const uint32_t brow = wn * 64 + lrow16;
            #pragma unroll
            for (int nb = 0; nb < 4; nb++)
                ldsm_x4(bw[nb], base + 2 * PLANE_BYTES + (brow + nb * 16) * ROWB + kb);
            // pass 1: A_hi * B  (16 independent MMAs)
            #pragma unroll
            for (int f = 0; f < 2; f++)
                #pragma unroll
                for (int j = 0; j < 8; j++) {
                    const int nb = j >> 1, sl = j & 1;
                    mma16816(acc[f][j], ah[f], bw[nb][sl], bw[nb][sl + 2]);
                }
            // pass 2: A_lo * B
            #pragma unroll
            for (int f = 0; f < 2; f++)
                #pragma unroll
                for (int j = 0; j < 8; j++) {
                    const int nb = j >> 1, sl = j & 1;
                    mma16816(acc[f][j], al[f], bw[nb][sl], bw[nb][sl + 2]);
                }
        }
    }

    // ---- epilogue: direct register -> global, fused ----
    const int r0 = lid >> 2;
    const int c0 = (lid & 3) * 2;
    #pragma unroll
    for (int f = 0; f < 2; f++) {
        #pragma unroll
        for (int j = 0; j < 8; j++) {
            const int row = blockIdx.y * 128 + wm * 32 + f * 16 + r0;
            const int col = blockIdx.x * 128 + wn * 64 + j * 8 + c0;
            #pragma unroll
            for (int hh = 0; hh < 2; hh++) {
                const size_t goff = (size_t)(row + hh * 8) * N + col;
                float p0 = acc[f][j][hh * 2 + 0];
                float p1 = acc[f][j][hh * 2 + 1];
                if (EPI == 1) {
                    float a0 = fmaxf(p0, 0.f), a1 = fmaxf(p1, 0.f);
                    float s0 = a0 * a0, s1 = a1 * a1;
                    __half h0 = __float2half_rn(s0), h1 = __float2half_rn(s1);
                    float l0 = s0 - __half2float(h0);
                    float l1 = s1 - __half2float(h1);
                    uint32_t hi = ((uint32_t)__half_as_ushort(h1) << 16)
                                |  (uint32_t)__half_as_ushort(h0);
                    uint32_t lo;
                    asm("cvt.rn.f16x2.f32 %0, %1, %2;"
                        : "=r"(lo) : "f"(l1), "f"(l0));
                    *(uint32_t*)(Ohi + goff) = hi;
                    *(uint32_t*)(Olo + goff) = lo;
                } else {
                    float2 o;
                    if (EPI == 0) {
                        o = make_float2(p0, p1);
                    } else if (EPI == 2) {
                        float2 rs = *(const float2*)(Res + goff);
                        o = make_float2(rs.x + p0, rs.y + p1);
                    } else {
                        float2 rs = *(const float2*)(Res + goff);
                        float2 ax = *(const float2*)(Aux + goff);
                        o.x = rs.x + ax.x / (1.f + __expf(-p0));
                        o.y = rs.y + ax.y / (1.f + __expf(-p1));
                    }
                    *(float2*)(C + goff) = o;
                }
            }
        }
    }
}

// ---------------- weight convert: fp32 -> fp16 plane -------------------------
__global__ void __launch_bounds__(256) wcvt_kernel(const float* __restrict__ w,
                                                   ushort16* __restrict__ hi,
                                                   int n4) {
    const int i4 = blockIdx.x * 256 + threadIdx.x;
    if (i4 >= n4) return;
    float4 a = ((const float4*)w)[i4];
    uint2 h;
    asm("cvt.rn.f16x2.f32 %0, %1, %2;" : "=r"(h.x) : "f"(a.y), "f"(a.x));
    asm("cvt.rn.f16x2.f32 %0, %1, %2;" : "=r"(h.y) : "f"(a.w), "f"(a.z));
    ((uint2*)hi)[i4] = h;
}

// ---------------- LayerNorm: one block per token row -------------------------
__global__ void __launch_bounds__(256) ln_kernel(const float* __restrict__ x,
                                                 const float* __restrict__ w,
                                                 const float* __restrict__ b,
                                                 float* __restrict__ out) {
    __shared__ float red[16];
    const int row = blockIdx.x;
    const int tid = threadIdx.x;
    const float4* xr = (const float4*)(x + (size_t)row * CDIM);
    float4 v = xr[tid];
    float s = v.x + v.y + v.z + v.w;
    float q = v.x*v.x + v.y*v.y + v.z*v.z + v.w*v.w;
    #pragma unroll
    for (int o = 16; o > 0; o >>= 1) {
        s += __shfl_xor_sync(0xffffffffu, s, o);
        q += __shfl_xor_sync(0xffffffffu, q, o);
    }
    const int lane = tid & 31, wd = tid >> 5;
    if (lane == 0) { red[wd] = s; red[8 + wd] = q; }
    __syncthreads();
    if (tid == 0) {
        float S = 0.f, Q = 0.f;
        #pragma unroll
        for (int i = 0; i < 8; i++) { S += red[i]; Q += red[8 + i]; }
        red[0] = S; red[8] = Q;
    }
    __syncthreads();
    const float mean = red[0] * (1.f / CDIM);
    const float var  = red[8] * (1.f / CDIM) - mean * mean;
    const float rstd = rsqrtf(var + 1e-5f);
    float4 w4 = ((const float4*)w)[tid];
    float4 b4 = ((const float4*)b)[tid];
    float4 o;
    o.x = (v.x - mean) * rstd * w4.x + b4.x;
    o.y = (v.y - mean) * rstd * w4.y + b4.y;
    o.z = (v.z - mean) * rstd * w4.z + b4.z;
    o.w = (v.w - mean) * rstd * w4.w + b4.w;
    ((float4*)(out + (size_t)row * CDIM))[tid] = o;
}

// ---------------- token-shift mixing (3 outputs, fp16 hi/lo planes) ----------
__global__ void __launch_bounds__(256) mix3_kernel(const float* __restrict__ h,
        const float* __restrict__ tk, const float* __restrict__ tv,
        const float* __restrict__ tr,
        ushort16* __restrict__ xkh, ushort16* __restrict__ xkl,
        ushort16* __restrict__ xvh, ushort16* __restrict__ xvl,
        ushort16* __restrict__ xrh, ushort16* __restrict__ xrl) {
    const size_t idx = (size_t)blockIdx.x * 256 + threadIdx.x;
    const int c = (int)(idx & (CDIM - 1));
    const int t = (int)((idx >> 10) & (TLEN - 1));
    const float hv = h[idx];
    const float pv = (t == 0) ? 0.f : h[idx - CDIM];
    const float d = hv - pv;
    split_store(xkh, xkl, idx, fmaf(tk[c], d, pv));
    split_store(xvh, xvl, idx, fmaf(tv[c], d, pv));
    split_store(xrh, xrl, idx, fmaf(tr[c], d, pv));
}

// ---------------- token-shift mixing (2 outputs, fp16 hi/lo planes) ----------
__global__ void __launch_bounds__(256) mix2_kernel(const float* __restrict__ h,
        const float* __restrict__ tk, const float* __restrict__ tr,
        ushort16* __restrict__ xkh, ushort16* __restrict__ xkl,
        ushort16* __restrict__ xrh, ushort16* __restrict__ xrl) {
    const size_t idx = (size_t)blockIdx.x * 256 + threadIdx.x;
    const int c = (int)(idx & (CDIM - 1));
    const int t = (int)((idx >> 10) & (TLEN - 1));
    const float hv = h[idx];
    const float pv = (t == 0) ? 0.f : h[idx - CDIM];
    const float d = hv - pv;
    split_store(xkh, xkl, idx, fmaf(tk[c], d, pv));
    split_store(xrh, xrl, idx, fmaf(tr[c], d, pv));
}

// ---------------- WKV recurrence, software-pipelined (depth 8) ---------------
__global__ void __launch_bounds__(64) wkv_kernel(const float* __restrict__ td,
                                                 const float* __restrict__ tf,
                                                 const float* __restrict__ k,
                                                 const float* __restrict__ v,
                                                 const float* __restrict__ r,
                                                 ushort16* __restrict__ yh,
                                                 ushort16* __restrict__ yl) {
    const int gid = blockIdx.x * 64 + threadIdx.x;     // < NB*CDIM
    const int c = gid & (CDIM - 1);
    const int b = gid >> 10;
    const float w = -__expf(td[c]);
    const float u = tf[c];
    float aa = 0.f, bb = 0.f, pp = -1e38f;
    const size_t base = (size_t)b * TLEN * CDIM + c;

    const int P = 8;
    float kp[P], vp[P], rp[P];
    #pragma unroll
    for (int j = 0; j < P; j++) {
        const size_t i = base + (size_t)j * CDIM;
        kp[j] = k[i]; vp[j] = v[i]; rp[j] = r[i];
    }

    for (int t0 = 0; t0 < TLEN; t0 += P) {
        const bool more = (t0 + P) < TLEN;
        #pragma unroll
        for (int j = 0; j < P; j++) {
            const size_t i = base + (size_t)(t0 + j) * CDIM;
            const float kt = kp[j], vt = vp[j], rr = rp[j];
            if (more) {
                const size_t ip = i + (size_t)P * CDIM;
                kp[j] = k[ip]; vp[j] = v[ip]; rp[j] = r[ip];
            }
            const float ww = u + kt;
            const float qq = fmaxf(pp, ww);
            const float e1 = __expf(pp - qq);
            const float e2 = __expf(ww - qq);
            const float yt = (e1 * aa + e2 * vt) / (e1 * bb + e2);
            const float yo = yt / (1.f + __expf(-rr));
            split_store(yh, yl, i, yo);
            const float w2 = pp + w;
            const float q2 = fmaxf(w2, kt);
            const float e1b = __expf(w2 - q2);
            const float e2b = __expf(kt - q2);
            aa = e1b * aa + e2b * vt;
            bb = e1b * bb + e2b;
            pp = q2;
        }
    }
}

// ---------------- host orchestration ----------------------------------------
extern "C" void kernel_launch(void* const* d_in, const int* in_sizes, int n_in,
                              void* d_out, int out_size) {
    const float* x     = (const float*)d_in[0];
    const float* ln1w  = (const float*)d_in[1];
    const float* ln1b  = (const float*)d_in[2];
    const float* ln2w  = (const float*)d_in[3];
    const float* ln2b  = (const float*)d_in[4];
    const float* atmk  = (const float*)d_in[5];
    const float* atmv  = (const float*)d_in[6];
    const float* atmr  = (const float*)d_in[7];
    const float* tdec  = (const float*)d_in[8];
    const float* tfst  = (const float*)d_in[9];
    const float* Wk    = (const float*)d_in[10];
    const float* Wv    = (const float*)d_in[11];
    const float* Wr    = (const float*)d_in[12];
    const float* Wo    = (const float*)d_in[13];
    const float* ftmk  = (const float*)d_in[14];
    const float* ftmr  = (const float*)d_in[15];
    const float* Wkey  = (const float*)d_in[16];
    const float* Wrec  = (const float*)d_in[17];
    const float* Wval  = (const float*)d_in[18];
    float* out = (float*)d_out;

    float *h, *kb, *vb, *rb, *kvb;
    ushort16 *xkh, *xkl, *xvh, *xvl, *xrh, *xrl, *yh, *yl, *kkh, *kkl, *wh;
    cudaGetSymbolAddress((void**)&h,   g_h);
    cudaGetSymbolAddress((void**)&kb,  g_k);
    cudaGetSymbolAddress((void**)&vb,  g_v);
    cudaGetSymbolAddress((void**)&rb,  g_r);
    cudaGetSymbolAddress((void**)&kvb, g_kv);
    cudaGetSymbolAddress((void**)&xkh, g_xk_h); cudaGetSymbolAddress((void**)&xkl, g_xk_l);
    cudaGetSymbolAddress((void**)&xvh, g_xv_h); cudaGetSymbolAddress((void**)&xvl, g_xv_l);
    cudaGetSymbolAddress((void**)&xrh, g_xr_h); cudaGetSymbolAddress((void**)&xrl, g_xr_l);
    cudaGetSymbolAddress((void**)&yh,  g_y_h);  cudaGetSymbolAddress((void**)&yl,  g_y_l);
    cudaGetSymbolAddress((void**)&kkh, g_kk_h); cudaGetSymbolAddress((void**)&kkl, g_kk_l);
    cudaGetSymbolAddress((void**)&wh,  g_w_h);

    cudaFuncSetAttribute(hmma_gemm_kernel<0>, cudaFuncAttributeMaxDynamicSharedMemorySize, GEMM_SMEM_BYTES);
    cudaFuncSetAttribute(hmma_gemm_kernel<1>, cudaFuncAttributeMaxDynamicSharedMemorySize, GEMM_SMEM_BYTES);
    cudaFuncSetAttribute(hmma_gemm_kernel<2>, cudaFuncAttributeMaxDynamicSharedMemorySize, GEMM_SMEM_BYTES);
    cudaFuncSetAttribute(hmma_gemm_kernel<3>, cudaFuncAttributeMaxDynamicSharedMemorySize, GEMM_SMEM_BYTES);

    // weight plane offsets (elements)
    const size_t OW_K = 0,        OW_V = 1048576,  OW_R = 2097152,
                 OW_O = 3145728,  OW_REC = 4194304,
                 OW_KEY = 5242880, OW_VAL = 9437184;
    const int CC4 = (CDIM * CDIM) / 4;          // 262144
    const int CF4 = (CDIM * FDIM) / 4;          // 1048576

    // weight fp16 conversion (rerun every call for determinism)
    wcvt_kernel<<<CC4 / 256, 256>>>(Wk,   wh + OW_K,   CC4);
    wcvt_kernel<<<CC4 / 256, 256>>>(Wv,   wh + OW_V,   CC4);
    wcvt_kernel<<<CC4 / 256, 256>>>(Wr,   wh + OW_R,   CC4);
    wcvt_kernel<<<CC4 / 256, 256>>>(Wo,   wh + OW_O,   CC4);
    wcvt_kernel<<<CC4 / 256, 256>>>(Wrec, wh + OW_REC, CC4);
    wcvt_kernel<<<CF4 / 256, 256>>>(Wkey, wh + OW_KEY, CF4);
    wcvt_kernel<<<CF4 / 256, 256>>>(Wval, wh + OW_VAL, CF4);

    const int elemBlocks = (BT * CDIM) / 256;    // 65536
    const dim3 gC(CDIM / 128, BT / 128);         // (8, 128)
    const dim3 gF(FDIM / 128, BT / 128);         // (32, 128)

    // ---- attention half ----
    ln_kernel<<<BT, 256>>>(x, ln1w, ln1b, h);
    mix3_kernel<<<elemBlocks, 256>>>(h, atmk, atmv, atmr, xkh, xkl, xvh, xvl, xrh, xrl);
    hmma_gemm_kernel<0><<<gC, 256, GEMM_SMEM_BYTES>>>(BT, CDIM, CDIM,
        xkh, xkl, wh + OW_K, kb, nullptr, nullptr, nullptr, nullptr);
    hmma_gemm_kernel<0><<<gC, 256, GEMM_SMEM_BYTES>>>(BT, CDIM, CDIM,
        xvh, xvl, wh + OW_V, vb, nullptr, nullptr, nullptr, nullptr);
    hmma_gemm_kernel<0><<<gC, 256, GEMM_SMEM_BYTES>>>(BT, CDIM, CDIM,
        xrh, xrl, wh + OW_R, rb, nullptr, nullptr, nullptr, nullptr);
    wkv_kernel<<<(NB * CDIM) / 64, 64>>>(tdec, tfst, kb, vb, rb, yh, yl);
    hmma_gemm_kernel<2><<<gC, 256, GEMM_SMEM_BYTES>>>(BT, CDIM, CDIM,
        yh, yl, wh + OW_O, out, nullptr, nullptr, x, nullptr);

    // ---- FFN half ----
    ln_kernel<<<BT, 256>>>(out, ln2w, ln2b, h);
    mix2_kernel<<<elemBlocks, 256>>>(h, ftmk, ftmr, xkh, xkl, xrh, xrl);
    hmma_gemm_kernel<1><<<gF, 256, GEMM_SMEM_BYTES>>>(BT, FDIM, CDIM,
        xkh, xkl, wh + OW_KEY, nullptr, kkh, kkl, nullptr, nullptr);
    hmma_gemm_kernel<0><<<gC, 256, GEMM_SMEM_BYTES>>>(BT, CDIM, FDIM,
        kkh, kkl, wh + OW_VAL, kvb, nullptr, nullptr, nullptr, nullptr);
    hmma_gemm_kernel<3><<<gC, 256, GEMM_SMEM_BYTES>>>(BT, CDIM, CDIM,
        xrh, xrl, wh + OW_REC, out, nullptr, nullptr, out, kvb);
}

// round 14
// speedup vs baseline: 3.4451x; 1.1304x over previous
#include <cuda_runtime.h>
#include <cuda_bf16.h>
#include <cuda_fp16.h>
#include <cstdint>
#include <cstddef>

// ---------------- problem constants ----------------
#define NB    8
#define TLEN  2048
#define CDIM  1024
#define FDIM  4096
#define BT    (NB * TLEN)        // 16384 tokens

typedef unsigned short ushort16;

// ---------------- scratch (static device globals; no allocations allowed) ----
__device__ float g_h [BT * CDIM];
__device__ float g_k [BT * CDIM];
__device__ float g_v [BT * CDIM];
__device__ float g_r [BT * CDIM];
__device__ float g_kv[BT * CDIM];
__device__ ushort16 g_xk_h[BT * CDIM], g_xk_l[BT * CDIM];
__device__ ushort16 g_xv_h[BT * CDIM], g_xv_l[BT * CDIM];
__device__ ushort16 g_xr_h[BT * CDIM], g_xr_l[BT * CDIM];
__device__ ushort16 g_y_h [BT * CDIM], g_y_l [BT * CDIM];
__device__ ushort16 g_kk_h[(size_t)BT * FDIM], g_kk_l[(size_t)BT * FDIM];
__device__ ushort16 g_w_h[13631488];              // fp16 weights (all 7 mats)

// ============================================================================
// helpers
// ============================================================================
__device__ __forceinline__ uint32_t smem_u32(const void* p) {
    uint32_t a;
    asm("{ .reg .u64 t; cvta.to.shared.u64 t, %1; cvt.u32.u64 %0, t; }"
        : "=r"(a) : "l"(p));
    return a;
}
__device__ __forceinline__ void ldsm_x4(uint32_t* r, uint32_t addr) {
    asm volatile("ldmatrix.sync.aligned.m8n8.x4.shared.b16 {%0,%1,%2,%3}, [%4];"
        : "=r"(r[0]), "=r"(r[1]), "=r"(r[2]), "=r"(r[3]) : "r"(addr));
}
__device__ __forceinline__ void mma16816(float* d, const uint32_t* a,
                                         uint32_t b0, uint32_t b1) {
    asm volatile("mma.sync.aligned.m16n8k16.row.col.f32.f16.f16.f32 "
        "{%0,%1,%2,%3}, {%4,%5,%6,%7}, {%8,%9}, {%0,%1,%2,%3};"
        : "+f"(d[0]), "+f"(d[1]), "+f"(d[2]), "+f"(d[3])
        : "r"(a[0]), "r"(a[1]), "r"(a[2]), "r"(a[3]), "r"(b0), "r"(b1));
}
// fp16 hi/lo split store (hi = rn(x); lo = rn(x - hi), subtraction exact)
__device__ __forceinline__ void split_store(ushort16* __restrict__ hp,
                                            ushort16* __restrict__ lp,
                                            size_t i, float x) {
    __half h = __float2half_rn(x);
    hp[i] = __half_as_ushort(h);
    const float lo = x - __half2float(h);
    lp[i] = __half_as_ushort(__float2half_rn(lo));
}

// ============================================================================
// HMMA GEMM: C[M,N] = A[M,K] @ B[N,K]^T.  A in fp16 hi/lo planes, B in fp16.
// D = A_hi*B + A_lo*B (2 passes, fp32 accum).
// BM=128, BN=128, BK=32; 8 warps 4(m) x 2(n); 3-stage cp.async pipeline,
// 2 CTAs/SM (regs capped at 128) so LDSM and HMMA overlap across CTAs.
// EPI 0: C=acc  1: {Ohi,Olo}=split(relu(acc)^2)  2: C=Res+acc
// EPI 3: C=Res+sigmoid(acc)*Aux
// ============================================================================
#define ROWB        80               // 32 fp16 (64B) + 16B pad per SMEM row
#define PLANE_BYTES 10240            // 128 * 80
#define STG_BYTES   30720            // 3 planes (A_hi, A_lo, B)
#define NSTAGE      3
#define GEMM_SMEM_BYTES (NSTAGE * STG_BYTES)   // 92160 -> 2 CTAs/SM

template <int EPI>
__global__ void __launch_bounds__(256, 2) hmma_gemm_kernel(
    int M, int N, int K,
    const ushort16* __restrict__ Ah, const ushort16* __restrict__ Al,
    const ushort16* __restrict__ Bw,
    float* __restrict__ C,
    ushort16* __restrict__ Ohi, ushort16* __restrict__ Olo,
    const float* __restrict__ Res,
    const float* __restrict__ Aux)
{
    extern __shared__ __align__(128) char dynsmem[];
    const uint32_t sm = smem_u32(dynsmem);
    const int tid = threadIdx.x;
    const int wid = tid >> 5, lid = tid & 31;
    const int wm = wid >> 1, wn = wid & 1;

    const ushort16* gp0 = Ah + (size_t)(blockIdx.y * 128) * K;
    const ushort16* gp1 = Al + (size_t)(blockIdx.y * 128) * K;
    const ushort16* gp2 = Bw + (size_t)(blockIdx.x * 128) * K;

    float acc[2][8][4];
    #pragma unroll
    for (int f = 0; f < 2; f++)
        #pragma unroll
        for (int j = 0; j < 8; j++)
            #pragma unroll
            for (int c = 0; c < 4; c++) acc[f][j][c] = 0.f;

    const int ns = K >> 5;           // K / 32

    // cp.async fill of one stage: 3 planes x 128 rows x 64B = 1536 x 16B chunks
    auto issue = [&](int s, int buf) {
        const uint32_t base = sm + buf * STG_BYTES;
        #pragma unroll
        for (int i = 0; i < 6; i++) {
            const int plane = i >> 1;
            const int idx2 = ((i & 1) << 8) | tid;     // 0..511 within plane
            const int row = idx2 >> 2;
            const int kq  = idx2 & 3;                  // 16B chunk in k-row
            const ushort16* src =
                (plane == 0 ? gp0 : plane == 1 ? gp1 : gp2)
                + (size_t)row * K + s * 32 + kq * 8;
            const uint32_t dst = base + plane * PLANE_BYTES + row * ROWB + kq * 16;
            asm volatile("cp.async.cg.shared.global [%0], [%1], 16;"
                         :: "r"(dst), "l"(src) : "memory");
        }
        asm volatile("cp.async.commit_group;" ::: "memory");
    };

    issue(0, 0); issue(1, 1);

    const uint32_t lrow16 = (lid & 15);
    const uint32_t lhi16  = (lid >> 4) * 16;           // +16B for k8..15 mats

    int cbuf = 0;                     // compute buffer cursor (mod 3)
    for (int s = 0; s < ns; s++) {
        asm volatile("cp.async.wait_group 1;" ::: "memory");
        __syncthreads();
        if (s + 2 < ns) {
            int ib = cbuf + 2; if (ib >= 3) ib -= 3;
            issue(s + 2, ib);
        }

        const uint32_t base = sm + cbuf * STG_BYTES;
        #pragma unroll
        for (int ks = 0; ks < 2; ks++) {
            const uint32_t kb = ks * 32 + lhi16;
            uint32_t ah[2][4], al[2][4], bw[4][4];
            const uint32_t arow = wm * 32 + lrow16;
            ldsm_x4(ah[0], base + 0 * PLANE_BYTES + arow * ROWB + kb);
            ldsm_x4(ah[1], base + 0 * PLANE_BYTES + (arow + 16) * ROWB + kb);
            ldsm_x4(al[0], base + 1 * PLANE_BYTES + arow * ROWB + kb);
            ldsm_x4(al[1], base + 1 * PLANE_BYTES + (arow + 16) * ROWB + kb);
            const uint32_t brow = wn * 64 + lrow16;
            #pragma unroll
            for (int nb = 0; nb < 4; nb++)
                ldsm_x4(bw[nb], base + 2 * PLANE_BYTES + (brow + nb * 16) * ROWB + kb);
            // pass 1: A_hi * B  (16 independent MMAs)
            #pragma unroll
            for (int f = 0; f < 2; f++)
                #pragma unroll
                for (int j = 0; j < 8; j++) {
                    const int nb = j >> 1, sl = j & 1;
                    mma16816(acc[f][j], ah[f], bw[nb][sl], bw[nb][sl + 2]);
                }
            // pass 2: A_lo * B
            #pragma unroll
            for (int f = 0; f < 2; f++)
                #pragma unroll
                for (int j = 0; j < 8; j++) {
                    const int nb = j >> 1, sl = j & 1;
                    mma16816(acc[f][j], al[f], bw[nb][sl], bw[nb][sl + 2]);
                }
        }
        if (++cbuf == 3) cbuf = 0;
        __syncthreads();             // all warps done with cbuf before refill
    }

    // ---- epilogue: direct register -> global, fused ----
    const int r0 = lid >> 2;
    const int c0 = (lid & 3) * 2;
    #pragma unroll
    for (int f = 0; f < 2; f++) {
        #pragma unroll
        for (int j = 0; j < 8; j++) {
            const int row = blockIdx.y * 128 + wm * 32 + f * 16 + r0;
            const int col = blockIdx.x * 128 + wn * 64 + j * 8 + c0;
            #pragma unroll
            for (int hh = 0; hh < 2; hh++) {
                const size_t goff = (size_t)(row + hh * 8) * N + col;
                float p0 = acc[f][j][hh * 2 + 0];
                float p1 = acc[f][j][hh * 2 + 1];
                if (EPI == 1) {
                    float a0 = fmaxf(p0, 0.f), a1 = fmaxf(p1, 0.f);
                    float s0 = a0 * a0, s1 = a1 * a1;
                    __half h0 = __float2half_rn(s0), h1 = __float2half_rn(s1);
                    float l0 = s0 - __half2float(h0);
                    float l1 = s1 - __half2float(h1);
                    uint32_t hi = ((uint32_t)__half_as_ushort(h1) << 16)
                                |  (uint32_t)__half_as_ushort(h0);
                    uint32_t lo;
                    asm("cvt.rn.f16x2.f32 %0, %1, %2;"
                        : "=r"(lo) : "f"(l1), "f"(l0));
                    *(uint32_t*)(Ohi + goff) = hi;
                    *(uint32_t*)(Olo + goff) = lo;
                } else {
                    float2 o;
                    if (EPI == 0) {
                        o = make_float2(p0, p1);
                    } else if (EPI == 2) {
                        float2 rs = *(const float2*)(Res + goff);
                        o = make_float2(rs.x + p0, rs.y + p1);
                    } else {
                        float2 rs = *(const float2*)(Res + goff);
                        float2 ax = *(const float2*)(Aux + goff);
                        o.x = rs.x + ax.x / (1.f + __expf(-p0));
                        o.y = rs.y + ax.y / (1.f + __expf(-p1));
                    }
                    *(float2*)(C + goff) = o;
                }
            }
        }
    }
}

// ---------------- weight convert: fp32 -> fp16 plane -------------------------
__global__ void __launch_bounds__(256) wcvt_kernel(const float* __restrict__ w,
                                                   ushort16* __restrict__ hi,
                                                   int n4) {
    const int i4 = blockIdx.x * 256 + threadIdx.x;
    if (i4 >= n4) return;
    float4 a = ((const float4*)w)[i4];
    uint2 h;
    asm("cvt.rn.f16x2.f32 %0, %1, %2;" : "=r"(h.x) : "f"(a.y), "f"(a.x));
    asm("cvt.rn.f16x2.f32 %0, %1, %2;" : "=r"(h.y) : "f"(a.w), "f"(a.z));
    ((uint2*)hi)[i4] = h;
}

// ---------------- LayerNorm: one block per token row -------------------------
__global__ void __launch_bounds__(256) ln_kernel(const float* __restrict__ x,
                                                 const float* __restrict__ w,
                                                 const float* __restrict__ b,
                                                 float* __restrict__ out) {
    __shared__ float red[16];
    const int row = blockIdx.x;
    const int tid = threadIdx.x;
    const float4* xr = (const float4*)(x + (size_t)row * CDIM);
    float4 v = xr[tid];
    float s = v.x + v.y + v.z + v.w;
    float q = v.x*v.x + v.y*v.y + v.z*v.z + v.w*v.w;
    #pragma unroll
    for (int o = 16; o > 0; o >>= 1) {
        s += __shfl_xor_sync(0xffffffffu, s, o);
        q += __shfl_xor_sync(0xffffffffu, q, o);
    }
    const int lane = tid & 31, wd = tid >> 5;
    if (lane == 0) { red[wd] = s; red[8 + wd] = q; }
    __syncthreads();
    if (tid == 0) {
        float S = 0.f, Q = 0.f;
        #pragma unroll
        for (int i = 0; i < 8; i++) { S += red[i]; Q += red[8 + i]; }
        red[0] = S; red[8] = Q;
    }
    __syncthreads();
    const float mean = red[0] * (1.f / CDIM);
    const float var  = red[8] * (1.f / CDIM) - mean * mean;
    const float rstd = rsqrtf(var + 1e-5f);
    float4 w4 = ((const float4*)w)[tid];
    float4 b4 = ((const float4*)b)[tid];
    float4 o;
    o.x = (v.x - mean) * rstd * w4.x + b4.x;
    o.y = (v.y - mean) * rstd * w4.y + b4.y;
    o.z = (v.z - mean) * rstd * w4.z + b4.z;
    o.w = (v.w - mean) * rstd * w4.w + b4.w;
    ((float4*)(out + (size_t)row * CDIM))[tid] = o;
}

// ---------------- token-shift mixing (3 outputs, fp16 hi/lo planes) ----------
__global__ void __launch_bounds__(256) mix3_kernel(const float* __restrict__ h,
        const float* __restrict__ tk, const float* __restrict__ tv,
        const float* __restrict__ tr,
        ushort16* __restrict__ xkh, ushort16* __restrict__ xkl,
        ushort16* __restrict__ xvh, ushort16* __restrict__ xvl,
        ushort16* __restrict__ xrh, ushort16* __restrict__ xrl) {
    const size_t idx = (size_t)blockIdx.x * 256 + threadIdx.x;
    const int c = (int)(idx & (CDIM - 1));
    const int t = (int)((idx >> 10) & (TLEN - 1));
    const float hv = h[idx];
    const float pv = (t == 0) ? 0.f : h[idx - CDIM];
    const float d = hv - pv;
    split_store(xkh, xkl, idx, fmaf(tk[c], d, pv));
    split_store(xvh, xvl, idx, fmaf(tv[c], d, pv));
    split_store(xrh, xrl, idx, fmaf(tr[c], d, pv));
}

// ---------------- token-shift mixing (2 outputs, fp16 hi/lo planes) ----------
__global__ void __launch_bounds__(256) mix2_kernel(const float* __restrict__ h,
        const float* __restrict__ tk, const float* __restrict__ tr,
        ushort16* __restrict__ xkh, ushort16* __restrict__ xkl,
        ushort16* __restrict__ xrh, ushort16* __restrict__ xrl) {
    const size_t idx = (size_t)blockIdx.x * 256 + threadIdx.x;
    const int c = (int)(idx & (CDIM - 1));
    const int t = (int)((idx >> 10) & (TLEN - 1));
    const float hv = h[idx];
    const float pv = (t == 0) ? 0.f : h[idx - CDIM];
    const float d = hv - pv;
    split_store(xkh, xkl, idx, fmaf(tk[c], d, pv));
    split_store(xrh, xrl, idx, fmaf(tr[c], d, pv));
}

// ---------------- WKV recurrence, software-pipelined (depth 8) ---------------
__global__ void __launch_bounds__(64) wkv_kernel(const float* __restrict__ td,
                                                 const float* __restrict__ tf,
                                                 const float* __restrict__ k,
                                                 const float* __restrict__ v,
                                                 const float* __restrict__ r,
                                                 ushort16* __restrict__ yh,
                                                 ushort16* __restrict__ yl) {
    const int gid = blockIdx.x * 64 + threadIdx.x;     // < NB*CDIM
    const int c = gid & (CDIM - 1);
    const int b = gid >> 10;
    const float w = -__expf(td[c]);
    const float u = tf[c];
    float aa = 0.f, bb = 0.f, pp = -1e38f;
    const size_t base = (size_t)b * TLEN * CDIM + c;

    const int P = 8;
    float kp[P], vp[P], rp[P];
    #pragma unroll
    for (int j = 0; j < P; j++) {
        const size_t i = base + (size_t)j * CDIM;
        kp[j] = k[i]; vp[j] = v[i]; rp[j] = r[i];
    }

    for (int t0 = 0; t0 < TLEN; t0 += P) {
        const bool more = (t0 + P) < TLEN;
        #pragma unroll
        for (int j = 0; j < P; j++) {
            const size_t i = base + (size_t)(t0 + j) * CDIM;
            const float kt = kp[j], vt = vp[j], rr = rp[j];
            if (more) {
                const size_t ip = i + (size_t)P * CDIM;
                kp[j] = k[ip]; vp[j] = v[ip]; rp[j] = r[ip];
            }
            const float ww = u + kt;
            const float qq = fmaxf(pp, ww);
            const float e1 = __expf(pp - qq);
            const float e2 = __expf(ww - qq);
            const float yt = (e1 * aa + e2 * vt) / (e1 * bb + e2);
            const float yo = yt / (1.f + __expf(-rr));
            split_store(yh, yl, i, yo);
            const float w2 = pp + w;
            const float q2 = fmaxf(w2, kt);
            const float e1b = __expf(w2 - q2);
            const float e2b = __expf(kt - q2);
            aa = e1b * aa + e2b * vt;
            bb = e1b * bb + e2b;
            pp = q2;
        }
    }
}

// ---------------- host orchestration ----------------------------------------
extern "C" void kernel_launch(void* const* d_in, const int* in_sizes, int n_in,
                              void* d_out, int out_size) {
    const float* x     = (const float*)d_in[0];
    const float* ln1w  = (const float*)d_in[1];
    const float* ln1b  = (const float*)d_in[2];
    const float* ln2w  = (const float*)d_in[3];
    const float* ln2b  = (const float*)d_in[4];
    const float* atmk  = (const float*)d_in[5];
    const float* atmv  = (const float*)d_in[6];
    const float* atmr  = (const float*)d_in[7];
    const float* tdec  = (const float*)d_in[8];
    const float* tfst  = (const float*)d_in[9];
    const float* Wk    = (const float*)d_in[10];
    const float* Wv    = (const float*)d_in[11];
    const float* Wr    = (const float*)d_in[12];
    const float* Wo    = (const float*)d_in[13];
    const float* ftmk  = (const float*)d_in[14];
    const float* ftmr  = (const float*)d_in[15];
    const float* Wkey  = (const float*)d_in[16];
    const float* Wrec  = (const float*)d_in[17];
    const float* Wval  = (const float*)d_in[18];
    float* out = (float*)d_out;

    float *h, *kb, *vb, *rb, *kvb;
    ushort16 *xkh, *xkl, *xvh, *xvl, *xrh, *xrl, *yh, *yl, *kkh, *kkl, *wh;
    cudaGetSymbolAddress((void**)&h,   g_h);
    cudaGetSymbolAddress((void**)&kb,  g_k);
    cudaGetSymbolAddress((void**)&vb,  g_v);
    cudaGetSymbolAddress((void**)&rb,  g_r);
    cudaGetSymbolAddress((void**)&kvb, g_kv);
    cudaGetSymbolAddress((void**)&xkh, g_xk_h); cudaGetSymbolAddress((void**)&xkl, g_xk_l);
    cudaGetSymbolAddress((void**)&xvh, g_xv_h); cudaGetSymbolAddress((void**)&xvl, g_xv_l);
    cudaGetSymbolAddress((void**)&xrh, g_xr_h); cudaGetSymbolAddress((void**)&xrl, g_xr_l);
    cudaGetSymbolAddress((void**)&yh,  g_y_h);  cudaGetSymbolAddress((void**)&yl,  g_y_l);
    cudaGetSymbolAddress((void**)&kkh, g_kk_h); cudaGetSymbolAddress((void**)&kkl, g_kk_l);
    cudaGetSymbolAddress((void**)&wh,  g_w_h);

    cudaFuncSetAttribute(hmma_gemm_kernel<0>, cudaFuncAttributeMaxDynamicSharedMemorySize, GEMM_SMEM_BYTES);
    cudaFuncSetAttribute(hmma_gemm_kernel<1>, cudaFuncAttributeMaxDynamicSharedMemorySize, GEMM_SMEM_BYTES);
    cudaFuncSetAttribute(hmma_gemm_kernel<2>, cudaFuncAttributeMaxDynamicSharedMemorySize, GEMM_SMEM_BYTES);
    cudaFuncSetAttribute(hmma_gemm_kernel<3>, cudaFuncAttributeMaxDynamicSharedMemorySize, GEMM_SMEM_BYTES);

    // weight plane offsets (elements)
    const size_t OW_K = 0,        OW_V = 1048576,  OW_R = 2097152,
                 OW_O = 3145728,  OW_REC = 4194304,
                 OW_KEY = 5242880, OW_VAL = 9437184;
    const int CC4 = (CDIM * CDIM) / 4;          // 262144
    const int CF4 = (CDIM * FDIM) / 4;          // 1048576

    // weight fp16 conversion (rerun every call for determinism)
    wcvt_kernel<<<CC4 / 256, 256>>>(Wk,   wh + OW_K,   CC4);
    wcvt_kernel<<<CC4 / 256, 256>>>(Wv,   wh + OW_V,   CC4);
    wcvt_kernel<<<CC4 / 256, 256>>>(Wr,   wh + OW_R,   CC4);
    wcvt_kernel<<<CC4 / 256, 256>>>(Wo,   wh + OW_O,   CC4);
    wcvt_kernel<<<CC4 / 256, 256>>>(Wrec, wh + OW_REC, CC4);
    wcvt_kernel<<<CF4 / 256, 256>>>(Wkey, wh + OW_KEY, CF4);
    wcvt_kernel<<<CF4 / 256, 256>>>(Wval, wh + OW_VAL, CF4);

    const int elemBlocks = (BT * CDIM) / 256;    // 65536
    const dim3 gC(CDIM / 128, BT / 128);         // (8, 128)
    const dim3 gF(FDIM / 128, BT / 128);         // (32, 128)

    // ---- attention half ----
    ln_kernel<<<BT, 256>>>(x, ln1w, ln1b, h);
    mix3_kernel<<<elemBlocks, 256>>>(h, atmk, atmv, atmr, xkh, xkl, xvh, xvl, xrh, xrl);
    hmma_gemm_kernel<0><<<gC, 256, GEMM_SMEM_BYTES>>>(BT, CDIM, CDIM,
        xkh, xkl, wh + OW_K, kb, nullptr, nullptr, nullptr, nullptr);
    hmma_gemm_kernel<0><<<gC, 256, GEMM_SMEM_BYTES>>>(BT, CDIM, CDIM,
        xvh, xvl, wh + OW_V, vb, nullptr, nullptr, nullptr, nullptr);
    hmma_gemm_kernel<0><<<gC, 256, GEMM_SMEM_BYTES>>>(BT, CDIM, CDIM,
        xrh, xrl, wh + OW_R, rb, nullptr, nullptr, nullptr, nullptr);
    wkv_kernel<<<(NB * CDIM) / 64, 64>>>(tdec, tfst, kb, vb, rb, yh, yl);
    hmma_gemm_kernel<2><<<gC, 256, GEMM_SMEM_BYTES>>>(BT, CDIM, CDIM,
        yh, yl, wh + OW_O, out, nullptr, nullptr, x, nullptr);

    // ---- FFN half ----
    ln_kernel<<<BT, 256>>>(out, ln2w, ln2b, h);
    mix2_kernel<<<elemBlocks, 256>>>(h, ftmk, ftmr, xkh, xkl, xrh, xrl);
    hmma_gemm_kernel<1><<<gF, 256, GEMM_SMEM_BYTES>>>(BT, FDIM, CDIM,
        xkh, xkl, wh + OW_KEY, nullptr, kkh, kkl, nullptr, nullptr);
    hmma_gemm_kernel<0><<<gC, 256, GEMM_SMEM_BYTES>>>(BT, CDIM, FDIM,
        kkh, kkl, wh + OW_VAL, kvb, nullptr, nullptr, nullptr, nullptr);
    hmma_gemm_kernel<3><<<gC, 256, GEMM_SMEM_BYTES>>>(BT, CDIM, CDIM,
        xrh, xrl, wh + OW_REC, out, nullptr, nullptr, out, kvb);
}

// round 15
// speedup vs baseline: 3.9516x; 1.1470x over previous
#include <cuda_runtime.h>
#include <cuda_bf16.h>
#include <cuda_fp16.h>
#include <cstdint>
#include <cstddef>

// ---------------- problem constants ----------------
#define NB    8
#define TLEN  2048
#define CDIM  1024
#define FDIM  4096
#define BT    (NB * TLEN)        // 16384 tokens
#define NCHUNK 16
#define CHUNKL (TLEN / NCHUNK)   // 128
#define NLANE  (NB * CDIM)       // 8192

typedef unsigned short ushort16;

// ---------------- scratch (static device globals; no allocations allowed) ----
__device__ float g_k [BT * CDIM];
__device__ float g_v [BT * CDIM];
__device__ float g_r [BT * CDIM];
__device__ float g_kv[BT * CDIM];
__device__ ushort16 g_xk_h[BT * CDIM], g_xk_l[BT * CDIM];
__device__ ushort16 g_xv_h[BT * CDIM], g_xv_l[BT * CDIM];
__device__ ushort16 g_xr_h[BT * CDIM], g_xr_l[BT * CDIM];
__device__ ushort16 g_y_h [BT * CDIM], g_y_l [BT * CDIM];
__device__ ushort16 g_kk_h[(size_t)BT * FDIM], g_kk_l[(size_t)BT * FDIM];
__device__ ushort16 g_w_h[13631488];              // fp16 weights (all 7 mats)
// wkv chunk-scan state
__device__ float g_ca[NCHUNK * NLANE], g_cb[NCHUNK * NLANE], g_cp[NCHUNK * NLANE];
__device__ float g_ia[NCHUNK * NLANE], g_ib[NCHUNK * NLANE], g_ip[NCHUNK * NLANE];

// ============================================================================
// helpers
// ============================================================================
__device__ __forceinline__ uint32_t smem_u32(const void* p) {
    uint32_t a;
    asm("{ .reg .u64 t; cvta.to.shared.u64 t, %1; cvt.u32.u64 %0, t; }"
        : "=r"(a) : "l"(p));
    return a;
}
__device__ __forceinline__ void ldsm_x4(uint32_t* r, uint32_t addr) {
    asm volatile("ldmatrix.sync.aligned.m8n8.x4.shared.b16 {%0,%1,%2,%3}, [%4];"
        : "=r"(r[0]), "=r"(r[1]), "=r"(r[2]), "=r"(r[3]) : "r"(addr));
}
__device__ __forceinline__ void mma16816(float* d, const uint32_t* a,
                                         uint32_t b0, uint32_t b1) {
    asm volatile("mma.sync.aligned.m16n8k16.row.col.f32.f16.f16.f32 "
        "{%0,%1,%2,%3}, {%4,%5,%6,%7}, {%8,%9}, {%0,%1,%2,%3};"
        : "+f"(d[0]), "+f"(d[1]), "+f"(d[2]), "+f"(d[3])
        : "r"(a[0]), "r"(a[1]), "r"(a[2]), "r"(a[3]), "r"(b0), "r"(b1));
}
// fp16 hi/lo split store, single element
__device__ __forceinline__ void split_store(ushort16* __restrict__ hp,
                                            ushort16* __restrict__ lp,
                                            size_t i, float x) {
    __half h = __float2half_rn(x);
    hp[i] = __half_as_ushort(h);
    const float lo = x - __half2float(h);
    lp[i] = __half_as_ushort(__float2half_rn(lo));
}
// fp16 hi/lo split store, 4 consecutive elements (vectorized)
__device__ __forceinline__ void split_store4(ushort16* __restrict__ hp,
                                             ushort16* __restrict__ lp,
                                             size_t i, float4 v) {
    __half h0 = __float2half_rn(v.x), h1 = __float2half_rn(v.y);
    __half h2 = __float2half_rn(v.z), h3 = __float2half_rn(v.w);
    float l0 = v.x - __half2float(h0), l1 = v.y - __half2float(h1);
    float l2 = v.z - __half2float(h2), l3 = v.w - __half2float(h3);
    uint2 hh, ll;
    hh.x = ((uint32_t)__half_as_ushort(h1) << 16) | (uint32_t)__half_as_ushort(h0);
    hh.y = ((uint32_t)__half_as_ushort(h3) << 16) | (uint32_t)__half_as_ushort(h2);
    asm("cvt.rn.f16x2.f32 %0, %1, %2;" : "=r"(ll.x) : "f"(l1), "f"(l0));
    asm("cvt.rn.f16x2.f32 %0, %1, %2;" : "=r"(ll.y) : "f"(l3), "f"(l2));
    *(uint2*)(hp + i) = hh;
    *(uint2*)(lp + i) = ll;
}

// ============================================================================
// HMMA GEMM (unchanged from R14): fp16 hi/lo A, fp16 B, 2-pass, fp32 accum.
// BM=128, BN=128, BK=32; 8 warps 4(m) x 2(n); 3-stage cp.async; 2 CTAs/SM.
// ============================================================================
#define ROWB        80
#define PLANE_BYTES 10240
#define STG_BYTES   30720
#define NSTAGE      3
#define GEMM_SMEM_BYTES (NSTAGE * STG_BYTES)   // 92160

template <int EPI>
__global__ void __launch_bounds__(256, 2) hmma_gemm_kernel(
    int M, int N, int K,
    const ushort16* __restrict__ Ah, const ushort16* __restrict__ Al,
    const ushort16* __restrict__ Bw,
    float* __restrict__ C,
    ushort16* __restrict__ Ohi, ushort16* __restrict__ Olo,
    const float* __restrict__ Res,
    const float* __restrict__ Aux)
{
    extern __shared__ __align__(128) char dynsmem[];
    const uint32_t sm = smem_u32(dynsmem);
    const int tid = threadIdx.x;
    const int wid = tid >> 5, lid = tid & 31;
    const int wm = wid >> 1, wn = wid & 1;

    const ushort16* gp0 = Ah + (size_t)(blockIdx.y * 128) * K;
    const ushort16* gp1 = Al + (size_t)(blockIdx.y * 128) * K;
    const ushort16* gp2 = Bw + (size_t)(blockIdx.x * 128) * K;

    float acc[2][8][4];
    #pragma unroll
    for (int f = 0; f < 2; f++)
        #pragma unroll
        for (int j = 0; j < 8; j++)
            #pragma unroll
            for (int c = 0; c < 4; c++) acc[f][j][c] = 0.f;

    const int ns = K >> 5;

    auto issue = [&](int s, int buf) {
        const uint32_t base = sm + buf * STG_BYTES;
        #pragma unroll
        for (int i = 0; i < 6; i++) {
            const int plane = i >> 1;
            const int idx2 = ((i & 1) << 8) | tid;
            const int row = idx2 >> 2;
            const int kq  = idx2 & 3;
            const ushort16* src =
                (plane == 0 ? gp0 : plane == 1 ? gp1 : gp2)
                + (size_t)row * K + s * 32 + kq * 8;
            const uint32_t dst = base + plane * PLANE_BYTES + row * ROWB + kq * 16;
            asm volatile("cp.async.cg.shared.global [%0], [%1], 16;"
                         :: "r"(dst), "l"(src) : "memory");
        }
        asm volatile("cp.async.commit_group;" ::: "memory");
    };

    issue(0, 0); issue(1, 1);

    const uint32_t lrow16 = (lid & 15);
    const uint32_t lhi16  = (lid >> 4) * 16;

    int cbuf = 0;
    for (int s = 0; s < ns; s++) {
        asm volatile("cp.async.wait_group 1;" ::: "memory");
        __syncthreads();
        if (s + 2 < ns) {
            int ib = cbuf + 2; if (ib >= 3) ib -= 3;
            issue(s + 2, ib);
        }

        const uint32_t base = sm + cbuf * STG_BYTES;
        #pragma unroll
        for (int ks = 0; ks < 2; ks++) {
            const uint32_t kb = ks * 32 + lhi16;
            uint32_t ah[2][4], al[2][4], bw[4][4];
            const uint32_t arow = wm * 32 + lrow16;
            ldsm_x4(ah[0], base + 0 * PLANE_BYTES + arow * ROWB + kb);
            ldsm_x4(ah[1], base + 0 * PLANE_BYTES + (arow + 16) * ROWB + kb);
            ldsm_x4(al[0], base + 1 * PLANE_BYTES + arow * ROWB + kb);
            ldsm_x4(al[1], base + 1 * PLANE_BYTES + (arow + 16) * ROWB + kb);
            const uint32_t brow = wn * 64 + lrow16;
            #pragma unroll
            for (int nb = 0; nb < 4; nb++)
                ldsm_x4(bw[nb], base + 2 * PLANE_BYTES + (brow + nb * 16) * ROWB + kb);
            #pragma unroll
            for (int f = 0; f < 2; f++)
                #pragma unroll
                for (int j = 0; j < 8; j++) {
                    const int nb = j >> 1, sl = j & 1;
                    mma16816(acc[f][j], ah[f], bw[nb][sl], bw[nb][sl + 2]);
                }
            #pragma unroll
            for (int f = 0; f < 2; f++)
                #pragma unroll
                for (int j = 0; j < 8; j++) {
                    const int nb = j >> 1, sl = j & 1;
                    mma16816(acc[f][j], al[f], bw[nb][sl], bw[nb][sl + 2]);
                }
        }
        if (++cbuf == 3) cbuf = 0;
        __syncthreads();
    }

    const int r0 = lid >> 2;
    const int c0 = (lid & 3) * 2;
    #pragma unroll
    for (int f = 0; f < 2; f++) {
        #pragma unroll
        for (int j = 0; j < 8; j++) {
            const int row = blockIdx.y * 128 + wm * 32 + f * 16 + r0;
            const int col = blockIdx.x * 128 + wn * 64 + j * 8 + c0;
            #pragma unroll
            for (int hh = 0; hh < 2; hh++) {
                const size_t goff = (size_t)(row + hh * 8) * N + col;
                float p0 = acc[f][j][hh * 2 + 0];
                float p1 = acc[f][j][hh * 2 + 1];
                if (EPI == 1) {
                    float a0 = fmaxf(p0, 0.f), a1 = fmaxf(p1, 0.f);
                    float s0 = a0 * a0, s1 = a1 * a1;
                    __half h0 = __float2half_rn(s0), h1 = __float2half_rn(s1);
                    float l0 = s0 - __half2float(h0);
                    float l1 = s1 - __half2float(h1);
                    uint32_t hi = ((uint32_t)__half_as_ushort(h1) << 16)
                                |  (uint32_t)__half_as_ushort(h0);
                    uint32_t lo;
                    asm("cvt.rn.f16x2.f32 %0, %1, %2;"
                        : "=r"(lo) : "f"(l1), "f"(l0));
                    *(uint32_t*)(Ohi + goff) = hi;
                    *(uint32_t*)(Olo + goff) = lo;
                } else {
                    float2 o;
                    if (EPI == 0) {
                        o = make_float2(p0, p1);
                    } else if (EPI == 2) {
                        float2 rs = *(const float2*)(Res + goff);
                        o = make_float2(rs.x + p0, rs.y + p1);
                    } else {
                        float2 rs = *(const float2*)(Res + goff);
                        float2 ax = *(const float2*)(Aux + goff);
                        o.x = rs.x + ax.x / (1.f + __expf(-p0));
                        o.y = rs.y + ax.y / (1.f + __expf(-p1));
                    }
                    *(float2*)(C + goff) = o;
                }
            }
        }
    }
}

// ---------------- weight convert: fp32 -> fp16 plane -------------------------
__global__ void __launch_bounds__(256) wcvt_kernel(const float* __restrict__ w,
                                                   ushort16* __restrict__ hi,
                                                   int n4) {
    const int i4 = blockIdx.x * 256 + threadIdx.x;
    if (i4 >= n4) return;
    float4 a = ((const float4*)w)[i4];
    uint2 h;
    asm("cvt.rn.f16x2.f32 %0, %1, %2;" : "=r"(h.x) : "f"(a.y), "f"(a.x));
    asm("cvt.rn.f16x2.f32 %0, %1, %2;" : "=r"(h.y) : "f"(a.w), "f"(a.z));
    ((uint2*)hi)[i4] = h;
}

// ============================================================================
// Fused LayerNorm + token-shift mix (LN of row t and t-1 recomputed in-block;
// t==0 previous is the ZERO vector, applied AFTER layernorm per time_shift).
// ============================================================================
__device__ __forceinline__ void dual_reduce(float4 vc, float4 vp,
                                            float* red, int tid,
                                            float& mean1, float& rstd1,
                                            float& mean2, float& rstd2) {
    float s1 = vc.x + vc.y + vc.z + vc.w;
    float q1 = vc.x*vc.x + vc.y*vc.y + vc.z*vc.z + vc.w*vc.w;
    float s2 = vp.x + vp.y + vp.z + vp.w;
    float q2 = vp.x*vp.x + vp.y*vp.y + vp.z*vp.z + vp.w*vp.w;
    #pragma unroll
    for (int o = 16; o > 0; o >>= 1) {
        s1 += __shfl_xor_sync(0xffffffffu, s1, o);
        q1 += __shfl_xor_sync(0xffffffffu, q1, o);
        s2 += __shfl_xor_sync(0xffffffffu, s2, o);
        q2 += __shfl_xor_sync(0xffffffffu, q2, o);
    }
    const int lane = tid & 31, wd = tid >> 5;
    if (lane == 0) { red[wd] = s1; red[8+wd] = q1; red[16+wd] = s2; red[24+wd] = q2; }
    __syncthreads();
    if (tid == 0) {
        float a = 0, b = 0, c = 0, d = 0;
        #pragma unroll
        for (int i = 0; i < 8; i++) { a += red[i]; b += red[8+i]; c += red[16+i]; d += red[24+i]; }
        red[0] = a; red[8] = b; red[16] = c; red[24] = d;
    }
    __syncthreads();
    mean1 = red[0] * (1.f / CDIM);
    float var1 = red[8] * (1.f / CDIM) - mean1 * mean1;
    rstd1 = rsqrtf(var1 + 1e-5f);
    mean2 = red[16] * (1.f / CDIM);
    float var2 = red[24] * (1.f / CDIM) - mean2 * mean2;
    rstd2 = rsqrtf(var2 + 1e-5f);
}

__global__ void __launch_bounds__(256) lnmix3_kernel(const float* __restrict__ x,
        const float* __restrict__ lw, const float* __restrict__ lb,
        const float* __restrict__ tk, const float* __restrict__ tv,
        const float* __restrict__ tr,
        ushort16* __restrict__ xkh, ushort16* __restrict__ xkl,
        ushort16* __restrict__ xvh, ushort16* __restrict__ xvl,
        ushort16* __restrict__ xrh, ushort16* __restrict__ xrl) {
    __shared__ float red[32];
    const int row = blockIdx.x;
    const int t = row & (TLEN - 1);
    const int tid = threadIdx.x;
    float4 vc = ((const float4*)(x + (size_t)row * CDIM))[tid];
    float4 vp = make_float4(0.f, 0.f, 0.f, 0.f);
    if (t) vp = ((const float4*)(x + (size_t)(row - 1) * CDIM))[tid];
    float m1, r1, m2, r2;
    dual_reduce(vc, vp, red, tid, m1, r1, m2, r2);
    float4 w4 = ((const float4*)lw)[tid];
    float4 b4 = ((const float4*)lb)[tid];
    float4 cn, pn;
    cn.x = (vc.x - m1) * r1 * w4.x + b4.x;  cn.y = (vc.y - m1) * r1 * w4.y + b4.y;
    cn.z = (vc.z - m1) * r1 * w4.z + b4.z;  cn.w = (vc.w - m1) * r1 * w4.w + b4.w;
    if (t) {
        pn.x = (vp.x - m2) * r2 * w4.x + b4.x;  pn.y = (vp.y - m2) * r2 * w4.y + b4.y;
        pn.z = (vp.z - m2) * r2 * w4.z + b4.z;  pn.w = (vp.w - m2) * r2 * w4.w + b4.w;
    } else pn = make_float4(0.f, 0.f, 0.f, 0.f);
    float4 dd = make_float4(cn.x - pn.x, cn.y - pn.y, cn.z - pn.z, cn.w - pn.w);
    const size_t i = (size_t)row * CDIM + tid * 4;
    float4 t4;
    t4 = ((const float4*)tk)[tid];
    split_store4(xkh, xkl, i, make_float4(fmaf(t4.x, dd.x, pn.x), fmaf(t4.y, dd.y, pn.y),
                                          fmaf(t4.z, dd.z, pn.z), fmaf(t4.w, dd.w, pn.w)));
    t4 = ((const float4*)tv)[tid];
    split_store4(xvh, xvl, i, make_float4(fmaf(t4.x, dd.x, pn.x), fmaf(t4.y, dd.y, pn.y),
                                          fmaf(t4.z, dd.z, pn.z), fmaf(t4.w, dd.w, pn.w)));
    t4 = ((const float4*)tr)[tid];
    split_store4(xrh, xrl, i, make_float4(fmaf(t4.x, dd.x, pn.x), fmaf(t4.y, dd.y, pn.y),
                                          fmaf(t4.z, dd.z, pn.z), fmaf(t4.w, dd.w, pn.w)));
}

__global__ void __launch_bounds__(256) lnmix2_kernel(const float* __restrict__ x,
        const float* __restrict__ lw, const float* __restrict__ lb,
        const float* __restrict__ tk, const float* __restrict__ tr,
        ushort16* __restrict__ xkh, ushort16* __restrict__ xkl,
        ushort16* __restrict__ xrh, ushort16* __restrict__ xrl) {
    __shared__ float red[32];
    const int row = blockIdx.x;
    const int t = row & (TLEN - 1);
    const int tid = threadIdx.x;
    float4 vc = ((const float4*)(x + (size_t)row * CDIM))[tid];
    float4 vp = make_float4(0.f, 0.f, 0.f, 0.f);
    if (t) vp = ((const float4*)(x + (size_t)(row - 1) * CDIM))[tid];
    float m1, r1, m2, r2;
    dual_reduce(vc, vp, red, tid, m1, r1, m2, r2);
    float4 w4 = ((const float4*)lw)[tid];
    float4 b4 = ((const float4*)lb)[tid];
    float4 cn, pn;
    cn.x = (vc.x - m1) * r1 * w4.x + b4.x;  cn.y = (vc.y - m1) * r1 * w4.y + b4.y;
    cn.z = (vc.z - m1) * r1 * w4.z + b4.z;  cn.w = (vc.w - m1) * r1 * w4.w + b4.w;
    if (t) {
        pn.x = (vp.x - m2) * r2 * w4.x + b4.x;  pn.y = (vp.y - m2) * r2 * w4.y + b4.y;
        pn.z = (vp.z - m2) * r2 * w4.z + b4.z;  pn.w = (vp.w - m2) * r2 * w4.w + b4.w;
    } else pn = make_float4(0.f, 0.f, 0.f, 0.f);
    float4 dd = make_float4(cn.x - pn.x, cn.y - pn.y, cn.z - pn.z, cn.w - pn.w);
    const size_t i = (size_t)row * CDIM + tid * 4;
    float4 t4;
    t4 = ((const float4*)tk)[tid];
    split_store4(xkh, xkl, i, make_float4(fmaf(t4.x, dd.x, pn.x), fmaf(t4.y, dd.y, pn.y),
                                          fmaf(t4.z, dd.z, pn.z), fmaf(t4.w, dd.w, pn.w)));
    t4 = ((const float4*)tr)[tid];
    split_store4(xrh, xrl, i, make_float4(fmaf(t4.x, dd.x, pn.x), fmaf(t4.y, dd.y, pn.y),
                                          fmaf(t4.z, dd.z, pn.z), fmaf(t4.w, dd.w, pn.w)));
}

// ============================================================================
// WKV chunked scan over T: the state recurrence A_t = e^w A_{t-1} + e^{k_t} v_t
// is linear, so chunk maps compose. 3 passes, NC=16 chunks of L=128.
// State repr (a, b, p): true A = a*e^p, B = b*e^p.
// ============================================================================
__global__ void __launch_bounds__(128) wkv_pass1(const float* __restrict__ td,
        const float* __restrict__ k, const float* __restrict__ v,
        float* __restrict__ Ca, float* __restrict__ Cb, float* __restrict__ Cp) {
    const int gid = blockIdx.x * 128 + threadIdx.x;    // < NLANE*NCHUNK
    const int c = gid & (CDIM - 1);
    const int rest = gid >> 10;                        // 0..127
    const int b = rest & (NB - 1);
    const int ch = rest >> 3;
    const float w = -__expf(td[c]);
    float a = 0.f, bb = 0.f, p = -1e38f;
    const size_t base = ((size_t)b * TLEN + ch * CHUNKL) * CDIM + c;
    #pragma unroll 4
    for (int t = 0; t < CHUNKL; t++) {
        const size_t i = base + (size_t)t * CDIM;
        const float kt = k[i], vt = v[i];
        const float w2 = p + w;
        const float q = fmaxf(w2, kt);
        const float e1 = __expf(w2 - q);
        const float e2 = __expf(kt - q);
        a = e1 * a + e2 * vt;
        bb = e1 * bb + e2;
        p = q;
    }
    const int st = ch * NLANE + b * CDIM + c;
    Ca[st] = a; Cb[st] = bb; Cp[st] = p;
}

__global__ void __launch_bounds__(256) wkv_pass2(const float* __restrict__ td,
        const float* __restrict__ Ca, const float* __restrict__ Cb,
        const float* __restrict__ Cp,
        float* __restrict__ Ia, float* __restrict__ Ib, float* __restrict__ Ip) {
    const int gid = blockIdx.x * 256 + threadIdx.x;    // < NLANE (== b*CDIM + c)
    const int c = gid & (CDIM - 1);
    const float wL = -__expf(td[c]) * (float)CHUNKL;
    float a = 0.f, bb = 0.f, p = -1e38f;
    for (int ch = 0; ch < NCHUNK; ch++) {
        const int st = ch * NLANE + gid;
        Ia[st] = a; Ib[st] = bb; Ip[st] = p;
        const float P1 = p + wL;
        const float cp = Cp[st];
        const float q = fmaxf(P1, cp);
        const float e1 = __expf(P1 - q);
        const float e2 = __expf(cp - q);
        a = e1 * a + e2 * Ca[st];
        bb = e1 * bb + e2 * Cb[st];
        p = q;
    }
}

__global__ void __launch_bounds__(128) wkv_pass3(const float* __restrict__ td,
        const float* __restrict__ tf,
        const float* __restrict__ k, const float* __restrict__ v,
        const float* __restrict__ r,
        const float* __restrict__ Ia, const float* __restrict__ Ib,
        const float* __restrict__ Ip,
        ushort16* __restrict__ yh, ushort16* __restrict__ yl) {
    const int gid = blockIdx.x * 128 + threadIdx.x;
    const int c = gid & (CDIM - 1);
    const int rest = gid >> 10;
    const int b = rest & (NB - 1);
    const int ch = rest >> 3;
    const float w = -__expf(td[c]);
    const float u = tf[c];
    const int st = ch * NLANE + b * CDIM + c;
    float aa = Ia[st], bb = Ib[st], pp = Ip[st];
    const size_t base = ((size_t)b * TLEN + ch * CHUNKL) * CDIM + c;
    #pragma unroll 4
    for (int t = 0; t < CHUNKL; t++) {
        const size_t i = base + (size_t)t * CDIM;
        const float kt = k[i], vt = v[i], rr = r[i];
        const float ww = u + kt;
        const float qq = fmaxf(pp, ww);
        const float e1 = __expf(pp - qq);
        const float e2 = __expf(ww - qq);
        const float yt = (e1 * aa + e2 * vt) / (e1 * bb + e2);
        const float yo = yt / (1.f + __expf(-rr));
        split_store(yh, yl, i, yo);
        const float w2 = pp + w;
        const float q2 = fmaxf(w2, kt);
        const float e1b = __expf(w2 - q2);
        const float e2b = __expf(kt - q2);
        aa = e1b * aa + e2b * vt;
        bb = e1b * bb + e2b;
        pp = q2;
    }
}

// ---------------- host orchestration ----------------------------------------
extern "C" void kernel_launch(void* const* d_in, const int* in_sizes, int n_in,
                              void* d_out, int out_size) {
    const float* x     = (const float*)d_in[0];
    const float* ln1w  = (const float*)d_in[1];
    const float* ln1b  = (const float*)d_in[2];
    const float* ln2w  = (const float*)d_in[3];
    const float* ln2b  = (const float*)d_in[4];
    const float* atmk  = (const float*)d_in[5];
    const float* atmv  = (const float*)d_in[6];
    const float* atmr  = (const float*)d_in[7];
    const float* tdec  = (const float*)d_in[8];
    const float* tfst  = (const float*)d_in[9];
    const float* Wk    = (const float*)d_in[10];
    const float* Wv    = (const float*)d_in[11];
    const float* Wr    = (const float*)d_in[12];
    const float* Wo    = (const float*)d_in[13];
    const float* ftmk  = (const float*)d_in[14];
    const float* ftmr  = (const float*)d_in[15];
    const float* Wkey  = (const float*)d_in[16];
    const float* Wrec  = (const float*)d_in[17];
    const float* Wval  = (const float*)d_in[18];
    float* out = (float*)d_out;

    float *kb, *vb, *rb, *kvb, *ca, *cb, *cp, *ia, *ib, *ip;
    ushort16 *xkh, *xkl, *xvh, *xvl, *xrh, *xrl, *yh, *yl, *kkh, *kkl, *wh;
    cudaGetSymbolAddress((void**)&kb,  g_k);
    cudaGetSymbolAddress((void**)&vb,  g_v);
    cudaGetSymbolAddress((void**)&rb,  g_r);
    cudaGetSymbolAddress((void**)&kvb, g_kv);
    cudaGetSymbolAddress((void**)&ca,  g_ca); cudaGetSymbolAddress((void**)&cb, g_cb);
    cudaGetSymbolAddress((void**)&cp,  g_cp);
    cudaGetSymbolAddress((void**)&ia,  g_ia); cudaGetSymbolAddress((void**)&ib, g_ib);
    cudaGetSymbolAddress((void**)&ip,  g_ip);
    cudaGetSymbolAddress((void**)&xkh, g_xk_h); cudaGetSymbolAddress((void**)&xkl, g_xk_l);
    cudaGetSymbolAddress((void**)&xvh, g_xv_h); cudaGetSymbolAddress((void**)&xvl, g_xv_l);
    cudaGetSymbolAddress((void**)&xrh, g_xr_h); cudaGetSymbolAddress((void**)&xrl, g_xr_l);
    cudaGetSymbolAddress((void**)&yh,  g_y_h);  cudaGetSymbolAddress((void**)&yl,  g_y_l);
    cudaGetSymbolAddress((void**)&kkh, g_kk_h); cudaGetSymbolAddress((void**)&kkl, g_kk_l);
    cudaGetSymbolAddress((void**)&wh,  g_w_h);

    cudaFuncSetAttribute(hmma_gemm_kernel<0>, cudaFuncAttributeMaxDynamicSharedMemorySize, GEMM_SMEM_BYTES);
    cudaFuncSetAttribute(hmma_gemm_kernel<1>, cudaFuncAttributeMaxDynamicSharedMemorySize, GEMM_SMEM_BYTES);
    cudaFuncSetAttribute(hmma_gemm_kernel<2>, cudaFuncAttributeMaxDynamicSharedMemorySize, GEMM_SMEM_BYTES);
    cudaFuncSetAttribute(hmma_gemm_kernel<3>, cudaFuncAttributeMaxDynamicSharedMemorySize, GEMM_SMEM_BYTES);

    const size_t OW_K = 0,        OW_V = 1048576,  OW_R = 2097152,
                 OW_O = 3145728,  OW_REC = 4194304,
                 OW_KEY = 5242880, OW_VAL = 9437184;
    const int CC4 = (CDIM * CDIM) / 4;
    const int CF4 = (CDIM * FDIM) / 4;

    wcvt_kernel<<<CC4 / 256, 256>>>(Wk,   wh + OW_K,   CC4);
    wcvt_kernel<<<CC4 / 256, 256>>>(Wv,   wh + OW_V,   CC4);
    wcvt_kernel<<<CC4 / 256, 256>>>(Wr,   wh + OW_R,   CC4);
    wcvt_kernel<<<CC4 / 256, 256>>>(Wo,   wh + OW_O,   CC4);
    wcvt_kernel<<<CC4 / 256, 256>>>(Wrec, wh + OW_REC, CC4);
    wcvt_kernel<<<CF4 / 256, 256>>>(Wkey, wh + OW_KEY, CF4);
    wcvt_kernel<<<CF4 / 256, 256>>>(Wval, wh + OW_VAL, CF4);

    const dim3 gC(CDIM / 128, BT / 128);         // (8, 128)
    const dim3 gF(FDIM / 128, BT / 128);         // (32, 128)
    const int scanBlocks = (NLANE * NCHUNK) / 128;   // 1024

    // ---- attention half ----
    lnmix3_kernel<<<BT, 256>>>(x, ln1w, ln1b, atmk, atmv, atmr,
                               xkh, xkl, xvh, xvl, xrh, xrl);
    hmma_gemm_kernel<0><<<gC, 256, GEMM_SMEM_BYTES>>>(BT, CDIM, CDIM,
        xkh, xkl, wh + OW_K, kb, nullptr, nullptr, nullptr, nullptr);
    hmma_gemm_kernel<0><<<gC, 256, GEMM_SMEM_BYTES>>>(BT, CDIM, CDIM,
        xvh, xvl, wh + OW_V, vb, nullptr, nullptr, nullptr, nullptr);
    hmma_gemm_kernel<0><<<gC, 256, GEMM_SMEM_BYTES>>>(BT, CDIM, CDIM,
        xrh, xrl, wh + OW_R, rb, nullptr, nullptr, nullptr, nullptr);
    wkv_pass1<<<scanBlocks, 128>>>(tdec, kb, vb, ca, cb, cp);
    wkv_pass2<<<NLANE / 256, 256>>>(tdec, ca, cb, cp, ia, ib, ip);
    wkv_pass3<<<scanBlocks, 128>>>(tdec, tfst, kb, vb, rb, ia, ib, ip, yh, yl);
    hmma_gemm_kernel<2><<<gC, 256, GEMM_SMEM_BYTES>>>(BT, CDIM, CDIM,
        yh, yl, wh + OW_O, out, nullptr, nullptr, x, nullptr);

    // ---- FFN half ----
    lnmix2_kernel<<<BT, 256>>>(out, ln2w, ln2b, ftmk, ftmr,
                               xkh, xkl, xrh, xrl);
    hmma_gemm_kernel<1><<<gF, 256, GEMM_SMEM_BYTES>>>(BT, FDIM, CDIM,
        xkh, xkl, wh + OW_KEY, nullptr, kkh, kkl, nullptr, nullptr);
    hmma_gemm_kernel<0><<<gC, 256, GEMM_SMEM_BYTES>>>(BT, CDIM, FDIM,
        kkh, kkl, wh + OW_VAL, kvb, nullptr, nullptr, nullptr, nullptr);
    hmma_gemm_kernel<3><<<gC, 256, GEMM_SMEM_BYTES>>>(BT, CDIM, CDIM,
        xrh, xrl, wh + OW_REC, out, nullptr, nullptr, out, kvb);
}

// round 16
// speedup vs baseline: 4.3879x; 1.1104x over previous
#include <cuda_runtime.h>
#include <cuda_bf16.h>
#include <cuda_fp16.h>
#include <cstdint>
#include <cstddef>

// ---------------- problem constants ----------------
#define NB    8
#define TLEN  2048
#define CDIM  1024
#define FDIM  4096
#define BT    (NB * TLEN)        // 16384 tokens
#define NCHUNK 16
#define CHUNKL (TLEN / NCHUNK)   // 128
#define NLANE  (NB * CDIM)       // 8192

typedef unsigned short ushort16;

// ---------------- scratch (static device globals; no allocations allowed) ----
__device__ float g_k [BT * CDIM];
__device__ float g_v [BT * CDIM];
__device__ float g_r [BT * CDIM];
__device__ float g_kv[BT * CDIM];
__device__ ushort16 g_xk[BT * CDIM];
__device__ ushort16 g_xv[BT * CDIM];
__device__ ushort16 g_xr[BT * CDIM];
__device__ ushort16 g_y [BT * CDIM];
__device__ ushort16 g_kk[(size_t)BT * FDIM];
__device__ ushort16 g_w_h[13631488];              // fp16 weights (all 7 mats)
// wkv chunk-scan state
__device__ float g_ca[NCHUNK * NLANE], g_cb[NCHUNK * NLANE], g_cp[NCHUNK * NLANE];
__device__ float g_ia[NCHUNK * NLANE], g_ib[NCHUNK * NLANE], g_ip[NCHUNK * NLANE];

// ============================================================================
// helpers
// ============================================================================
__device__ __forceinline__ uint32_t smem_u32(const void* p) {
    uint32_t a;
    asm("{ .reg .u64 t; cvta.to.shared.u64 t, %1; cvt.u32.u64 %0, t; }"
        : "=r"(a) : "l"(p));
    return a;
}
__device__ __forceinline__ void ldsm_x4(uint32_t* r, uint32_t addr) {
    asm volatile("ldmatrix.sync.aligned.m8n8.x4.shared.b16 {%0,%1,%2,%3}, [%4];"
        : "=r"(r[0]), "=r"(r[1]), "=r"(r[2]), "=r"(r[3]) : "r"(addr));
}
__device__ __forceinline__ void mma16816(float* d, const uint32_t* a,
                                         uint32_t b0, uint32_t b1) {
    asm volatile("mma.sync.aligned.m16n8k16.row.col.f32.f16.f16.f32 "
        "{%0,%1,%2,%3}, {%4,%5,%6,%7}, {%8,%9}, {%0,%1,%2,%3};"
        : "+f"(d[0]), "+f"(d[1]), "+f"(d[2]), "+f"(d[3])
        : "r"(a[0]), "r"(a[1]), "r"(a[2]), "r"(a[3]), "r"(b0), "r"(b1));
}
// fp16 store, 4 consecutive elements (vectorized)
__device__ __forceinline__ void h4_store(ushort16* __restrict__ hp,
                                         size_t i, float4 v) {
    uint2 hh;
    asm("cvt.rn.f16x2.f32 %0, %1, %2;" : "=r"(hh.x) : "f"(v.y), "f"(v.x));
    asm("cvt.rn.f16x2.f32 %0, %1, %2;" : "=r"(hh.y) : "f"(v.w), "f"(v.z));
    *(uint2*)(hp + i) = hh;
}

// ============================================================================
// HMMA GEMM: C[M,N] = A[M,K] @ B[N,K]^T, both operands single fp16, fp32 accum.
// BM=128, BN=128, BK=32; 8 warps 4(m) x 2(n); 4-stage cp.async; 2 CTAs/SM.
// EPI 0: C=acc  1: Oh=fp16(relu(acc)^2)  2: C=Res+acc  3: C=Res+sigmoid(acc)*Aux
// ============================================================================
#define ROWB        80               // 32 fp16 (64B) + 16B pad per SMEM row
#define PLANE_BYTES 10240            // 128 * 80
#define STG_BYTES   20480            // 2 planes (A, B)
#define NSTAGE      4
#define GEMM_SMEM_BYTES (NSTAGE * STG_BYTES)   // 81920 -> 2 CTAs/SM

template <int EPI>
__global__ void __launch_bounds__(256, 2) hmma_gemm_kernel(
    int M, int N, int K,
    const ushort16* __restrict__ Ah,
    const ushort16* __restrict__ Bw,
    float* __restrict__ C,
    ushort16* __restrict__ Oh,
    const float* __restrict__ Res,
    const float* __restrict__ Aux)
{
    extern __shared__ __align__(128) char dynsmem[];
    const uint32_t sm = smem_u32(dynsmem);
    const int tid = threadIdx.x;
    const int wid = tid >> 5, lid = tid & 31;
    const int wm = wid >> 1, wn = wid & 1;

    const ushort16* gp0 = Ah + (size_t)(blockIdx.y * 128) * K;
    const ushort16* gp1 = Bw + (size_t)(blockIdx.x * 128) * K;

    float acc[2][8][4];
    #pragma unroll
    for (int f = 0; f < 2; f++)
        #pragma unroll
        for (int j = 0; j < 8; j++)
            #pragma unroll
            for (int c = 0; c < 4; c++) acc[f][j][c] = 0.f;

    const int ns = K >> 5;

    // cp.async fill: 2 planes x 128 rows x 64B = 1024 x 16B chunks
    auto issue = [&](int s, int buf) {
        const uint32_t base = sm + buf * STG_BYTES;
        #pragma unroll
        for (int i = 0; i < 4; i++) {
            const int plane = i >> 1;
            const int idx2 = ((i & 1) << 8) | tid;     // 0..511 within plane
            const int row = idx2 >> 2;
            const int kq  = idx2 & 3;
            const ushort16* src = (plane == 0 ? gp0 : gp1)
                + (size_t)row * K + s * 32 + kq * 8;
            const uint32_t dst = base + plane * PLANE_BYTES + row * ROWB + kq * 16;
            asm volatile("cp.async.cg.shared.global [%0], [%1], 16;"
                         :: "r"(dst), "l"(src) : "memory");
        }
        asm volatile("cp.async.commit_group;" ::: "memory");
    };

    issue(0, 0); issue(1, 1); issue(2, 2);

    const uint32_t lrow16 = (lid & 15);
    const uint32_t lhi16  = (lid >> 4) * 16;

    int cbuf = 0;
    for (int s = 0; s < ns; s++) {
        asm volatile("cp.async.wait_group 2;" ::: "memory");
        __syncthreads();
        if (s + 3 < ns) issue(s + 3, (cbuf + 3) & 3);

        const uint32_t base = sm + cbuf * STG_BYTES;
        #pragma unroll
        for (int ks = 0; ks < 2; ks++) {
            const uint32_t kb = ks * 32 + lhi16;
            uint32_t ah[2][4], bw[4][4];
            const uint32_t arow = wm * 32 + lrow16;
            ldsm_x4(ah[0], base + arow * ROWB + kb);
            ldsm_x4(ah[1], base + (arow + 16) * ROWB + kb);
            const uint32_t brow = wn * 64 + lrow16;
            #pragma unroll
            for (int nb = 0; nb < 4; nb++)
                ldsm_x4(bw[nb], base + PLANE_BYTES + (brow + nb * 16) * ROWB + kb);
            #pragma unroll
            for (int f = 0; f < 2; f++)
                #pragma unroll
                for (int j = 0; j < 8; j++) {
                    const int nb = j >> 1, sl = j & 1;
                    mma16816(acc[f][j], ah[f], bw[nb][sl], bw[nb][sl + 2]);
                }
        }
        cbuf = (cbuf + 1) & 3;
        __syncthreads();
    }

    // ---- epilogue: direct register -> global, fused ----
    const int r0 = lid >> 2;
    const int c0 = (lid & 3) * 2;
    #pragma unroll
    for (int f = 0; f < 2; f++) {
        #pragma unroll
        for (int j = 0; j < 8; j++) {
            const int row = blockIdx.y * 128 + wm * 32 + f * 16 + r0;
            const int col = blockIdx.x * 128 + wn * 64 + j * 8 + c0;
            #pragma unroll
            for (int hh = 0; hh < 2; hh++) {
                const size_t goff = (size_t)(row + hh * 8) * N + col;
                float p0 = acc[f][j][hh * 2 + 0];
                float p1 = acc[f][j][hh * 2 + 1];
                if (EPI == 1) {
                    float a0 = fmaxf(p0, 0.f), a1 = fmaxf(p1, 0.f);
                    float s0 = a0 * a0, s1 = a1 * a1;
                    uint32_t hv;
                    asm("cvt.rn.f16x2.f32 %0, %1, %2;"
                        : "=r"(hv) : "f"(s1), "f"(s0));
                    *(uint32_t*)(Oh + goff) = hv;
                } else {
                    float2 o;
                    if (EPI == 0) {
                        o = make_float2(p0, p1);
                    } else if (EPI == 2) {
                        float2 rs = *(const float2*)(Res + goff);
                        o = make_float2(rs.x + p0, rs.y + p1);
                    } else {
                        float2 rs = *(const float2*)(Res + goff);
                        float2 ax = *(const float2*)(Aux + goff);
                        o.x = rs.x + ax.x / (1.f + __expf(-p0));
                        o.y = rs.y + ax.y / (1.f + __expf(-p1));
                    }
                    *(float2*)(C + goff) = o;
                }
            }
        }
    }
}

// ---------------- weight convert: fp32 -> fp16 plane -------------------------
__global__ void __launch_bounds__(256) wcvt_kernel(const float* __restrict__ w,
                                                   ushort16* __restrict__ hi,
                                                   int n4) {
    const int i4 = blockIdx.x * 256 + threadIdx.x;
    if (i4 >= n4) return;
    float4 a = ((const float4*)w)[i4];
    uint2 h;
    asm("cvt.rn.f16x2.f32 %0, %1, %2;" : "=r"(h.x) : "f"(a.y), "f"(a.x));
    asm("cvt.rn.f16x2.f32 %0, %1, %2;" : "=r"(h.y) : "f"(a.w), "f"(a.z));
    ((uint2*)hi)[i4] = h;
}

// ============================================================================
// Fused LayerNorm + token-shift mix (fp16 outputs).
// t==0 previous is the ZERO vector, applied AFTER layernorm per time_shift.
// ============================================================================
__device__ __forceinline__ void dual_reduce(float4 vc, float4 vp,
                                            float* red, int tid,
                                            float& mean1, float& rstd1,
                                            float& mean2, float& rstd2) {
    float s1 = vc.x + vc.y + vc.z + vc.w;
    float q1 = vc.x*vc.x + vc.y*vc.y + vc.z*vc.z + vc.w*vc.w;
    float s2 = vp.x + vp.y + vp.z + vp.w;
    float q2 = vp.x*vp.x + vp.y*vp.y + vp.z*vp.z + vp.w*vp.w;
    #pragma unroll
    for (int o = 16; o > 0; o >>= 1) {
        s1 += __shfl_xor_sync(0xffffffffu, s1, o);
        q1 += __shfl_xor_sync(0xffffffffu, q1, o);
        s2 += __shfl_xor_sync(0xffffffffu, s2, o);
        q2 += __shfl_xor_sync(0xffffffffu, q2, o);
    }
    const int lane = tid & 31, wd = tid >> 5;
    if (lane == 0) { red[wd] = s1; red[8+wd] = q1; red[16+wd] = s2; red[24+wd] = q2; }
    __syncthreads();
    if (tid == 0) {
        float a = 0, b = 0, c = 0, d = 0;
        #pragma unroll
        for (int i = 0; i < 8; i++) { a += red[i]; b += red[8+i]; c += red[16+i]; d += red[24+i]; }
        red[0] = a; red[8] = b; red[16] = c; red[24] = d;
    }
    __syncthreads();
    mean1 = red[0] * (1.f / CDIM);
    float var1 = red[8] * (1.f / CDIM) - mean1 * mean1;
    rstd1 = rsqrtf(var1 + 1e-5f);
    mean2 = red[16] * (1.f / CDIM);
    float var2 = red[24] * (1.f / CDIM) - mean2 * mean2;
    rstd2 = rsqrtf(var2 + 1e-5f);
}

__global__ void __launch_bounds__(256) lnmix3_kernel(const float* __restrict__ x,
        const float* __restrict__ lw, const float* __restrict__ lb,
        const float* __restrict__ tk, const float* __restrict__ tv,
        const float* __restrict__ tr,
        ushort16* __restrict__ xk, ushort16* __restrict__ xv,
        ushort16* __restrict__ xr) {
    __shared__ float red[32];
    const int row = blockIdx.x;
    const int t = row & (TLEN - 1);
    const int tid = threadIdx.x;
    float4 vc = ((const float4*)(x + (size_t)row * CDIM))[tid];
    float4 vp = make_float4(0.f, 0.f, 0.f, 0.f);
    if (t) vp = ((const float4*)(x + (size_t)(row - 1) * CDIM))[tid];
    float m1, r1, m2, r2;
    dual_reduce(vc, vp, red, tid, m1, r1, m2, r2);
    float4 w4 = ((const float4*)lw)[tid];
    float4 b4 = ((const float4*)lb)[tid];
    float4 cn, pn;
    cn.x = (vc.x - m1) * r1 * w4.x + b4.x;  cn.y = (vc.y - m1) * r1 * w4.y + b4.y;
    cn.z = (vc.z - m1) * r1 * w4.z + b4.z;  cn.w = (vc.w - m1) * r1 * w4.w + b4.w;
    if (t) {
        pn.x = (vp.x - m2) * r2 * w4.x + b4.x;  pn.y = (vp.y - m2) * r2 * w4.y + b4.y;
        pn.z = (vp.z - m2) * r2 * w4.z + b4.z;  pn.w = (vp.w - m2) * r2 * w4.w + b4.w;
    } else pn = make_float4(0.f, 0.f, 0.f, 0.f);
    float4 dd = make_float4(cn.x - pn.x, cn.y - pn.y, cn.z - pn.z, cn.w - pn.w);
    const size_t i = (size_t)row * CDIM + tid * 4;
    float4 t4;
    t4 = ((const float4*)tk)[tid];
    h4_store(xk, i, make_float4(fmaf(t4.x, dd.x, pn.x), fmaf(t4.y, dd.y, pn.y),
                                fmaf(t4.z, dd.z, pn.z), fmaf(t4.w, dd.w, pn.w)));
    t4 = ((const float4*)tv)[tid];
    h4_store(xv, i, make_float4(fmaf(t4.x, dd.x, pn.x), fmaf(t4.y, dd.y, pn.y),
                                fmaf(t4.z, dd.z, pn.z), fmaf(t4.w, dd.w, pn.w)));
    t4 = ((const float4*)tr)[tid];
    h4_store(xr, i, make_float4(fmaf(t4.x, dd.x, pn.x), fmaf(t4.y, dd.y, pn.y),
                                fmaf(t4.z, dd.z, pn.z), fmaf(t4.w, dd.w, pn.w)));
}

__global__ void __launch_bounds__(256) lnmix2_kernel(const float* __restrict__ x,
        const float* __restrict__ lw, const float* __restrict__ lb,
        const float* __restrict__ tk, const float* __restrict__ tr,
        ushort16* __restrict__ xk, ushort16* __restrict__ xr) {
    __shared__ float red[32];
    const int row = blockIdx.x;
    const int t = row & (TLEN - 1);
    const int tid = threadIdx.x;
    float4 vc = ((const float4*)(x + (size_t)row * CDIM))[tid];
    float4 vp = make_float4(0.f, 0.f, 0.f, 0.f);
    if (t) vp = ((const float4*)(x + (size_t)(row - 1) * CDIM))[tid];
    float m1, r1, m2, r2;
    dual_reduce(vc, vp, red, tid, m1, r1, m2, r2);
    float4 w4 = ((const float4*)lw)[tid];
    float4 b4 = ((const float4*)lb)[tid];
    float4 cn, pn;
    cn.x = (vc.x - m1) * r1 * w4.x + b4.x;  cn.y = (vc.y - m1) * r1 * w4.y + b4.y;
    cn.z = (vc.z - m1) * r1 * w4.z + b4.z;  cn.w = (vc.w - m1) * r1 * w4.w + b4.w;
    if (t) {
        pn.x = (vp.x - m2) * r2 * w4.x + b4.x;  pn.y = (vp.y - m2) * r2 * w4.y + b4.y;
        pn.z = (vp.z - m2) * r2 * w4.z + b4.z;  pn.w = (vp.w - m2) * r2 * w4.w + b4.w;
    } else pn = make_float4(0.f, 0.f, 0.f, 0.f);
    float4 dd = make_float4(cn.x - pn.x, cn.y - pn.y, cn.z - pn.z, cn.w - pn.w);
    const size_t i = (size_t)row * CDIM + tid * 4;
    float4 t4;
    t4 = ((const float4*)tk)[tid];
    h4_store(xk, i, make_float4(fmaf(t4.x, dd.x, pn.x), fmaf(t4.y, dd.y, pn.y),
                                fmaf(t4.z, dd.z, pn.z), fmaf(t4.w, dd.w, pn.w)));
    t4 = ((const float4*)tr)[tid];
    h4_store(xr, i, make_float4(fmaf(t4.x, dd.x, pn.x), fmaf(t4.y, dd.y, pn.y),
                                fmaf(t4.z, dd.z, pn.z), fmaf(t4.w, dd.w, pn.w)));
}

// ============================================================================
// WKV chunked scan over T (3 passes, NC=16 chunks of L=128), y in fp16.
// ============================================================================
__global__ void __launch_bounds__(128) wkv_pass1(const float* __restrict__ td,
        const float* __restrict__ k, const float* __restrict__ v,
        float* __restrict__ Ca, float* __restrict__ Cb, float* __restrict__ Cp) {
    const int gid = blockIdx.x * 128 + threadIdx.x;
    const int c = gid & (CDIM - 1);
    const int rest = gid >> 10;
    const int b = rest & (NB - 1);
    const int ch = rest >> 3;
    const float w = -__expf(td[c]);
    float a = 0.f, bb = 0.f, p = -1e38f;
    const size_t base = ((size_t)b * TLEN + ch * CHUNKL) * CDIM + c;
    #pragma unroll 4
    for (int t = 0; t < CHUNKL; t++) {
        const size_t i = base + (size_t)t * CDIM;
        const float kt = k[i], vt = v[i];
        const float w2 = p + w;
        const float q = fmaxf(w2, kt);
        const float e1 = __expf(w2 - q);
        const float e2 = __expf(kt - q);
        a = e1 * a + e2 * vt;
        bb = e1 * bb + e2;
        p = q;
    }
    const int st = ch * NLANE + b * CDIM + c;
    Ca[st] = a; Cb[st] = bb; Cp[st] = p;
}

__global__ void __launch_bounds__(256) wkv_pass2(const float* __restrict__ td,
        const float* __restrict__ Ca, const float* __restrict__ Cb,
        const float* __restrict__ Cp,
        float* __restrict__ Ia, float* __restrict__ Ib, float* __restrict__ Ip) {
    const int gid = blockIdx.x * 256 + threadIdx.x;
    const int c = gid & (CDIM - 1);
    const float wL = -__expf(td[c]) * (float)CHUNKL;
    float a = 0.f, bb = 0.f, p = -1e38f;
    for (int ch = 0; ch < NCHUNK; ch++) {
        const int st = ch * NLANE + gid;
        Ia[st] = a; Ib[st] = bb; Ip[st] = p;
        const float P1 = p + wL;
        const float cp = Cp[st];
        const float q = fmaxf(P1, cp);
        const float e1 = __expf(P1 - q);
        const float e2 = __expf(cp - q);
        a = e1 * a + e2 * Ca[st];
        bb = e1 * bb + e2 * Cb[st];
        p = q;
    }
}

__global__ void __launch_bounds__(128) wkv_pass3(const float* __restrict__ td,
        const float* __restrict__ tf,
        const float* __restrict__ k, const float* __restrict__ v,
        const float* __restrict__ r,
        const float* __restrict__ Ia, const float* __restrict__ Ib,
        const float* __restrict__ Ip,
        ushort16* __restrict__ yh) {
    const int gid = blockIdx.x * 128 + threadIdx.x;
    const int c = gid & (CDIM - 1);
    const int rest = gid >> 10;
    const int b = rest & (NB - 1);
    const int ch = rest >> 3;
    const float w = -__expf(td[c]);
    const float u = tf[c];
    const int st = ch * NLANE + b * CDIM + c;
    float aa = Ia[st], bb = Ib[st], pp = Ip[st];
    const size_t base = ((size_t)b * TLEN + ch * CHUNKL) * CDIM + c;
    #pragma unroll 4
    for (int t = 0; t < CHUNKL; t++) {
        const size_t i = base + (size_t)t * CDIM;
        const float kt = k[i], vt = v[i], rr = r[i];
        const float ww = u + kt;
        const float qq = fmaxf(pp, ww);
        const float e1 = __expf(pp - qq);
        const float e2 = __expf(ww - qq);
        const float yt = (e1 * aa + e2 * vt) / (e1 * bb + e2);
        const float yo = yt / (1.f + __expf(-rr));
        yh[i] = __half_as_ushort(__float2half_rn(yo));
        const float w2 = pp + w;
        const float q2 = fmaxf(w2, kt);
        const float e1b = __expf(w2 - q2);
        const float e2b = __expf(kt - q2);
        aa = e1b * aa + e2b * vt;
        bb = e1b * bb + e2b;
        pp = q2;
    }
}

// ---------------- host orchestration ----------------------------------------
extern "C" void kernel_launch(void* const* d_in, const int* in_sizes, int n_in,
                              void* d_out, int out_size) {
    const float* x     = (const float*)d_in[0];
    const float* ln1w  = (const float*)d_in[1];
    const float* ln1b  = (const float*)d_in[2];
    const float* ln2w  = (const float*)d_in[3];
    const float* ln2b  = (const float*)d_in[4];
    const float* atmk  = (const float*)d_in[5];
    const float* atmv  = (const float*)d_in[6];
    const float* atmr  = (const float*)d_in[7];
    const float* tdec  = (const float*)d_in[8];
    const float* tfst  = (const float*)d_in[9];
    const float* Wk    = (const float*)d_in[10];
    const float* Wv    = (const float*)d_in[11];
    const float* Wr    = (const float*)d_in[12];
    const float* Wo    = (const float*)d_in[13];
    const float* ftmk  = (const float*)d_in[14];
    const float* ftmr  = (const float*)d_in[15];
    const float* Wkey  = (const float*)d_in[16];
    const float* Wrec  = (const float*)d_in[17];
    const float* Wval  = (const float*)d_in[18];
    float* out = (float*)d_out;

    float *kb, *vb, *rb, *kvb, *ca, *cb, *cp, *ia, *ib, *ip;
    ushort16 *xk, *xv, *xr, *yh, *kk, *wh;
    cudaGetSymbolAddress((void**)&kb,  g_k);
    cudaGetSymbolAddress((void**)&vb,  g_v);
    cudaGetSymbolAddress((void**)&rb,  g_r);
    cudaGetSymbolAddress((void**)&kvb, g_kv);
    cudaGetSymbolAddress((void**)&ca,  g_ca); cudaGetSymbolAddress((void**)&cb, g_cb);
    cudaGetSymbolAddress((void**)&cp,  g_cp);
    cudaGetSymbolAddress((void**)&ia,  g_ia); cudaGetSymbolAddress((void**)&ib, g_ib);
    cudaGetSymbolAddress((void**)&ip,  g_ip);
    cudaGetSymbolAddress((void**)&xk,  g_xk);
    cudaGetSymbolAddress((void**)&xv,  g_xv);
    cudaGetSymbolAddress((void**)&xr,  g_xr);
    cudaGetSymbolAddress((void**)&yh,  g_y);
    cudaGetSymbolAddress((void**)&kk,  g_kk);
    cudaGetSymbolAddress((void**)&wh,  g_w_h);

    cudaFuncSetAttribute(hmma_gemm_kernel<0>, cudaFuncAttributeMaxDynamicSharedMemorySize, GEMM_SMEM_BYTES);
    cudaFuncSetAttribute(hmma_gemm_kernel<1>, cudaFuncAttributeMaxDynamicSharedMemorySize, GEMM_SMEM_BYTES);
    cudaFuncSetAttribute(hmma_gemm_kernel<2>, cudaFuncAttributeMaxDynamicSharedMemorySize, GEMM_SMEM_BYTES);
    cudaFuncSetAttribute(hmma_gemm_kernel<3>, cudaFuncAttributeMaxDynamicSharedMemorySize, GEMM_SMEM_BYTES);

    const size_t OW_K = 0,        OW_V = 1048576,  OW_R = 2097152,
                 OW_O = 3145728,  OW_REC = 4194304,
                 OW_KEY = 5242880, OW_VAL = 9437184;
    const int CC4 = (CDIM * CDIM) / 4;
    const int CF4 = (CDIM * FDIM) / 4;

    wcvt_kernel<<<CC4 / 256, 256>>>(Wk,   wh + OW_K,   CC4);
    wcvt_kernel<<<CC4 / 256, 256>>>(Wv,   wh + OW_V,   CC4);
    wcvt_kernel<<<CC4 / 256, 256>>>(Wr,   wh + OW_R,   CC4);
    wcvt_kernel<<<CC4 / 256, 256>>>(Wo,   wh + OW_O,   CC4);
    wcvt_kernel<<<CC4 / 256, 256>>>(Wrec, wh + OW_REC, CC4);
    wcvt_kernel<<<CF4 / 256, 256>>>(Wkey, wh + OW_KEY, CF4);
    wcvt_kernel<<<CF4 / 256, 256>>>(Wval, wh + OW_VAL, CF4);

    const dim3 gC(CDIM / 128, BT / 128);         // (8, 128)
    const dim3 gF(FDIM / 128, BT / 128);         // (32, 128)
    const int scanBlocks = (NLANE * NCHUNK) / 128;   // 1024

    // ---- attention half ----
    lnmix3_kernel<<<BT, 256>>>(x, ln1w, ln1b, atmk, atmv, atmr, xk, xv, xr);
    hmma_gemm_kernel<0><<<gC, 256, GEMM_SMEM_BYTES>>>(BT, CDIM, CDIM,
        xk, wh + OW_K, kb, nullptr, nullptr, nullptr);
    hmma_gemm_kernel<0><<<gC, 256, GEMM_SMEM_BYTES>>>(BT, CDIM, CDIM,
        xv, wh + OW_V, vb, nullptr, nullptr, nullptr);
    hmma_gemm_kernel<0><<<gC, 256, GEMM_SMEM_BYTES>>>(BT, CDIM, CDIM,
        xr, wh + OW_R, rb, nullptr, nullptr, nullptr);
    wkv_pass1<<<scanBlocks, 128>>>(tdec, kb, vb, ca, cb, cp);
    wkv_pass2<<<NLANE / 256, 256>>>(tdec, ca, cb, cp, ia, ib, ip);
    wkv_pass3<<<scanBlocks, 128>>>(tdec, tfst, kb, vb, rb, ia, ib, ip, yh);
    hmma_gemm_kernel<2><<<gC, 256, GEMM_SMEM_BYTES>>>(BT, CDIM, CDIM,
        yh, wh + OW_O, out, nullptr, x, nullptr);

    // ---- FFN half ----
    lnmix2_kernel<<<BT, 256>>>(out, ln2w, ln2b, ftmk, ftmr, xk, xr);
    hmma_gemm_kernel<1><<<gF, 256, GEMM_SMEM_BYTES>>>(BT, FDIM, CDIM,
        xk, wh + OW_KEY, nullptr, kk, nullptr, nullptr);
    hmma_gemm_kernel<0><<<gC, 256, GEMM_SMEM_BYTES>>>(BT, CDIM, FDIM,
        kk, wh + OW_VAL, kvb, nullptr, nullptr, nullptr);
    hmma_gemm_kernel<3><<<gC, 256, GEMM_SMEM_BYTES>>>(BT, CDIM, CDIM,
        xr, wh + OW_REC, out, nullptr, out, kvb);
}